// round 1
// baseline (speedup 1.0000x reference)
#include <cuda_runtime.h>

#define D 1024
#define H 16
#define HDIM 64
#define BATCH 2
#define SEQ 2048
#define MROWS (BATCH * SEQ) /* 4096 */

// Scratch (device globals: allocation-free per harness rules)
__device__ float g_Q[BATCH * H * SEQ * HDIM];
__device__ float g_K[BATCH * H * SEQ * HDIM];
__device__ float g_V[BATCH * H * SEQ * HDIM];
__device__ float g_ctx[MROWS * D];

// ============================================================
// SGEMM: C[M=4096, N=1024] = A @ W + bias
// 128x128 block tile, K-tile 8, 256 threads, 8x8 microtile.
// head_layout=1 scatters output to [B,H,S,HD] for attention.
// ============================================================
#define GBM 128
#define GBN 128
#define GBK 8
#define GTM 8
#define GTN 8

__global__ __launch_bounds__(256) void gemm_bias_kernel(
    const float* __restrict__ A, const float* __restrict__ W,
    const float* __restrict__ bias, float* __restrict__ Cout,
    int head_layout)
{
    __shared__ float As[GBK][GBM + 4];
    __shared__ float Bs[GBK][GBN + 4];

    const int tid = threadIdx.x;
    const int bm = blockIdx.y * GBM;
    const int bn = blockIdx.x * GBN;
    const int tx = tid & 15;
    const int ty = tid >> 4;

    // global->smem load mapping
    const int aRow = tid >> 1;         // 0..127
    const int aCol = (tid & 1) * 4;    // 0 or 4
    const int bRow = tid >> 5;         // 0..7
    const int bCol = (tid & 31) * 4;   // 0..124

    float acc[GTM][GTN];
#pragma unroll
    for (int i = 0; i < GTM; i++)
#pragma unroll
        for (int j = 0; j < GTN; j++) acc[i][j] = 0.0f;

    const float* Aptr = A + (size_t)(bm + aRow) * D + aCol;
    const float* Wptr = W + (size_t)bRow * D + bn + bCol;

    for (int k0 = 0; k0 < D; k0 += GBK) {
        float4 av = *reinterpret_cast<const float4*>(Aptr + k0);
        float4 wv = *reinterpret_cast<const float4*>(Wptr + (size_t)k0 * D);
        As[aCol + 0][aRow] = av.x;
        As[aCol + 1][aRow] = av.y;
        As[aCol + 2][aRow] = av.z;
        As[aCol + 3][aRow] = av.w;
        *reinterpret_cast<float4*>(&Bs[bRow][bCol]) = wv;
        __syncthreads();

#pragma unroll
        for (int kk = 0; kk < GBK; kk++) {
            float ar[GTM], br[GTN];
            *reinterpret_cast<float4*>(ar)     = *reinterpret_cast<const float4*>(&As[kk][ty * GTM]);
            *reinterpret_cast<float4*>(ar + 4) = *reinterpret_cast<const float4*>(&As[kk][ty * GTM + 4]);
            *reinterpret_cast<float4*>(br)     = *reinterpret_cast<const float4*>(&Bs[kk][tx * GTN]);
            *reinterpret_cast<float4*>(br + 4) = *reinterpret_cast<const float4*>(&Bs[kk][tx * GTN + 4]);
#pragma unroll
            for (int i = 0; i < GTM; i++)
#pragma unroll
                for (int j = 0; j < GTN; j++)
                    acc[i][j] += ar[i] * br[j];
        }
        __syncthreads();
    }

#pragma unroll
    for (int i = 0; i < GTM; i++) {
        const int m = bm + ty * GTM + i;
#pragma unroll
        for (int j = 0; j < GTN; j++) {
            const int n = bn + tx * GTN + j;
            const float v = acc[i][j] + bias[n];
            if (head_layout) {
                const int b = m >> 11;        // m / SEQ
                const int s = m & (SEQ - 1);
                const int h = n >> 6;         // n / HDIM
                const int hd = n & (HDIM - 1);
                Cout[(((size_t)(b * H + h)) * SEQ + s) * HDIM + hd] = v;
            } else {
                Cout[(size_t)m * D + n] = v;
            }
        }
    }
}

// ============================================================
// Flash attention (fp32): per block, 128 q-rows x full K sweep
// in 64-col tiles. 256 threads (16x16), 8x4 microtiles.
// Q pre-scaled by 1/sqrt(HD)=1/8. Online softmax, shuffle
// reductions across the 16-lane tx groups (half-warps).
// ============================================================
#define ABM 128
#define ABN 64
#define APAD 65

__global__ __launch_bounds__(256, 2) void attn_kernel(
    const float* __restrict__ Qg, const float* __restrict__ Kg,
    const float* __restrict__ Vg, float* __restrict__ ctx)
{
    extern __shared__ float smf[];
    float* Qs = smf;                       // 128*65
    float* Ks = Qs + ABM * APAD;           // 64*65
    float* Vs = Ks + ABN * APAD;           // 64*65
    float* Ps = Vs + ABN * APAD;           // 128*65

    const int tid = threadIdx.x;
    const int tx = tid & 15;
    const int ty = tid >> 4;
    const int qt = blockIdx.x;             // 0..15
    const int bh = blockIdx.y;             // 0..31

    // ---- load Q tile (scaled) ----
    {
        const int r = tid >> 1;
        const int dbase = (tid & 1) * 32;
        const float inv = 0.125f;  // 1/sqrt(64)
        const float* src = Qg + ((size_t)bh * SEQ + qt * ABM + r) * HDIM + dbase;
        float* dst = Qs + r * APAD + dbase;
#pragma unroll
        for (int c = 0; c < 8; c++) {
            float4 v = *reinterpret_cast<const float4*>(src + c * 4);
            dst[c * 4 + 0] = v.x * inv;
            dst[c * 4 + 1] = v.y * inv;
            dst[c * 4 + 2] = v.z * inv;
            dst[c * 4 + 3] = v.w * inv;
        }
    }

    float m_i[8], l_i[8], o[8][4];
#pragma unroll
    for (int i = 0; i < 8; i++) {
        m_i[i] = -1e30f;
        l_i[i] = 0.0f;
#pragma unroll
        for (int j = 0; j < 4; j++) o[i][j] = 0.0f;
    }

    const float* Kbase = Kg + (size_t)bh * SEQ * HDIM;
    const float* Vbase = Vg + (size_t)bh * SEQ * HDIM;

    for (int kt = 0; kt < SEQ / ABN; kt++) {
        __syncthreads();  // previous iteration's reads of Ks/Vs/Ps done
        // ---- load K/V tiles ----
        {
            const int r = tid >> 2;
            const int dbase = (tid & 3) * 16;
            const float* ksrc = Kbase + ((size_t)kt * ABN + r) * HDIM + dbase;
            const float* vsrc = Vbase + ((size_t)kt * ABN + r) * HDIM + dbase;
            float* kdst = Ks + r * APAD + dbase;
            float* vdst = Vs + r * APAD + dbase;
#pragma unroll
            for (int c = 0; c < 4; c++) {
                float4 kv = *reinterpret_cast<const float4*>(ksrc + c * 4);
                kdst[c * 4 + 0] = kv.x; kdst[c * 4 + 1] = kv.y;
                kdst[c * 4 + 2] = kv.z; kdst[c * 4 + 3] = kv.w;
                float4 vv = *reinterpret_cast<const float4*>(vsrc + c * 4);
                vdst[c * 4 + 0] = vv.x; vdst[c * 4 + 1] = vv.y;
                vdst[c * 4 + 2] = vv.z; vdst[c * 4 + 3] = vv.w;
            }
        }
        __syncthreads();

        // ---- scores: S = Qtile @ Ktile^T (pre-scaled) ----
        float s[8][4];
#pragma unroll
        for (int i = 0; i < 8; i++)
#pragma unroll
            for (int j = 0; j < 4; j++) s[i][j] = 0.0f;

        const float* qrow = Qs + ty * 8 * APAD;
        const float* kcol = Ks + tx * 4 * APAD;
#pragma unroll 8
        for (int d = 0; d < HDIM; d++) {
            float a[8], b[4];
#pragma unroll
            for (int i = 0; i < 8; i++) a[i] = qrow[i * APAD + d];
#pragma unroll
            for (int j = 0; j < 4; j++) b[j] = kcol[j * APAD + d];
#pragma unroll
            for (int i = 0; i < 8; i++)
#pragma unroll
                for (int j = 0; j < 4; j++) s[i][j] += a[i] * b[j];
        }

        // ---- online softmax update ----
#pragma unroll
        for (int i = 0; i < 8; i++) {
            float mx = fmaxf(fmaxf(s[i][0], s[i][1]), fmaxf(s[i][2], s[i][3]));
            mx = fmaxf(mx, __shfl_xor_sync(0xffffffffu, mx, 1));
            mx = fmaxf(mx, __shfl_xor_sync(0xffffffffu, mx, 2));
            mx = fmaxf(mx, __shfl_xor_sync(0xffffffffu, mx, 4));
            mx = fmaxf(mx, __shfl_xor_sync(0xffffffffu, mx, 8));
            const float mnew = fmaxf(m_i[i], mx);
            float p[4];
            float rs = 0.0f;
#pragma unroll
            for (int j = 0; j < 4; j++) {
                p[j] = __expf(s[i][j] - mnew);
                rs += p[j];
            }
            rs += __shfl_xor_sync(0xffffffffu, rs, 1);
            rs += __shfl_xor_sync(0xffffffffu, rs, 2);
            rs += __shfl_xor_sync(0xffffffffu, rs, 4);
            rs += __shfl_xor_sync(0xffffffffu, rs, 8);
            const float corr = __expf(m_i[i] - mnew);
            l_i[i] = l_i[i] * corr + rs;
            m_i[i] = mnew;
#pragma unroll
            for (int j = 0; j < 4; j++) {
                o[i][j] *= corr;
                Ps[(ty * 8 + i) * APAD + tx * 4 + j] = p[j];
            }
        }
        __syncthreads();

        // ---- PV: O += P @ Vtile ----
        const float* prow = Ps + ty * 8 * APAD;
        const float* vcol = Vs + tx * 4;
#pragma unroll 8
        for (int kc = 0; kc < ABN; kc++) {
            float a[8], b[4];
#pragma unroll
            for (int i = 0; i < 8; i++) a[i] = prow[i * APAD + kc];
#pragma unroll
            for (int j = 0; j < 4; j++) b[j] = vcol[kc * APAD + j];
#pragma unroll
            for (int i = 0; i < 8; i++)
#pragma unroll
                for (int j = 0; j < 4; j++) o[i][j] += a[i] * b[j];
        }
    }

    // ---- epilogue: normalize, write ctx in [B,S,D] (h-interleaved) ----
    const int bq = bh >> 4;
    const int h = bh & (H - 1);
#pragma unroll
    for (int i = 0; i < 8; i++) {
        const int srow = qt * ABM + ty * 8 + i;
        const float invl = 1.0f / l_i[i];
        float* dst = ctx + ((size_t)bq * SEQ + srow) * D + h * HDIM + tx * 4;
#pragma unroll
        for (int j = 0; j < 4; j++) dst[j] = o[i][j] * invl;
    }
}

// ============================================================
// Launch
// ============================================================
extern "C" void kernel_launch(void* const* d_in, const int* in_sizes, int n_in,
                              void* d_out, int out_size)
{
    const float* x  = (const float*)d_in[0];
    const float* Wq = (const float*)d_in[1];
    const float* bq = (const float*)d_in[2];
    const float* Wk = (const float*)d_in[3];
    const float* bk = (const float*)d_in[4];
    const float* Wv = (const float*)d_in[5];
    const float* bv = (const float*)d_in[6];
    const float* Wo = (const float*)d_in[7];
    const float* bo = (const float*)d_in[8];
    float* out = (float*)d_out;

    float *Qd, *Kd, *Vd, *Ctxd;
    cudaGetSymbolAddress((void**)&Qd, g_Q);
    cudaGetSymbolAddress((void**)&Kd, g_K);
    cudaGetSymbolAddress((void**)&Vd, g_V);
    cudaGetSymbolAddress((void**)&Ctxd, g_ctx);

    const dim3 ggrid(D / GBN, MROWS / GBM);  // (8, 32)
    gemm_bias_kernel<<<ggrid, 256>>>(x, Wq, bq, Qd, 1);
    gemm_bias_kernel<<<ggrid, 256>>>(x, Wk, bk, Kd, 1);
    gemm_bias_kernel<<<ggrid, 256>>>(x, Wv, bv, Vd, 1);

    const int attn_smem = (ABM * APAD + 2 * ABN * APAD + ABM * APAD) * (int)sizeof(float);
    cudaFuncSetAttribute(attn_kernel, cudaFuncAttributeMaxDynamicSharedMemorySize, attn_smem);
    attn_kernel<<<dim3(SEQ / ABM, BATCH * H), 256, attn_smem>>>(Qd, Kd, Vd, Ctxd);

    gemm_bias_kernel<<<ggrid, 256>>>(Ctxd, Wo, bo, out, 0);
}

// round 3
// speedup vs baseline: 1.5256x; 1.5256x over previous
#include <cuda_runtime.h>
#include <cstdint>

#define D 1024
#define H 16
#define HDIM 64
#define BATCH 2
#define SEQ 2048
#define MROWS (BATCH * SEQ) /* 4096 */

// ---------------- scratch (device globals; allocation-free) ----------------
__device__ float g_Q[BATCH * H * SEQ * HDIM];
__device__ float g_K[BATCH * H * SEQ * HDIM];
__device__ float g_V[BATCH * H * SEQ * HDIM];
__device__ float g_ctx[MROWS * D];
__device__ float g_Wt[4 * D * D];   // transposed (tf32-rounded) weights

// ---------------- helpers ----------------
__device__ __forceinline__ uint32_t smem_u32(const void* p) {
    uint32_t a;
    asm("{ .reg .u64 t; cvta.to.shared.u64 t, %1; cvt.u32.u64 %0, t; }"
        : "=r"(a) : "l"(p));
    return a;
}
__device__ __forceinline__ float tf32r(float x) {
    float r; asm("cvt.rna.tf32.f32 %0, %1;" : "=f"(r) : "f"(x)); return r;
}
__device__ __forceinline__ void cp_async16(uint32_t dst, const void* src) {
    asm volatile("cp.async.cg.shared.global [%0], [%1], 16;" :: "r"(dst), "l"(src));
}
#define CP_COMMIT() asm volatile("cp.async.commit_group;" ::: "memory")
#define CP_WAIT(n)  asm volatile("cp.async.wait_group %0;" :: "n"(n) : "memory")

__device__ __forceinline__ void mma_tf32(float* c, const uint32_t* a, const uint32_t* b) {
    asm volatile(
        "mma.sync.aligned.m16n8k8.row.col.f32.tf32.tf32.f32 "
        "{%0,%1,%2,%3}, {%4,%5,%6,%7}, {%8,%9}, {%0,%1,%2,%3};"
        : "+f"(c[0]), "+f"(c[1]), "+f"(c[2]), "+f"(c[3])
        : "r"(a[0]), "r"(a[1]), "r"(a[2]), "r"(a[3]), "r"(b[0]), "r"(b[1]));
}

// ============================================================
// Weight transpose: Wt[n][k] = tf32_rna(W[k][n])  (1024x1024)
// ============================================================
__global__ __launch_bounds__(256) void transpose_w(const float* __restrict__ W,
                                                   float* __restrict__ Wt) {
    __shared__ float t[32][33];
    const int bx = blockIdx.x * 32;   // n
    const int by = blockIdx.y * 32;   // k
    const int x = threadIdx.x;
    const int y = threadIdx.y;        // 0..7
#pragma unroll
    for (int i = 0; i < 4; i++)
        t[y + 8 * i][x] = tf32r(W[(size_t)(by + y + 8 * i) * D + bx + x]);
    __syncthreads();
#pragma unroll
    for (int i = 0; i < 4; i++)
        Wt[(size_t)(bx + y + 8 * i) * D + by + x] = t[x][y + 8 * i];
}

// ============================================================
// mma.sync tf32 GEMM: C[4096x1024] = A @ Wt^T + bias
//   A: [M, K] row-major, Wt: [N, K] row-major (pre-transposed W).
// CTA 128x128, K-chunk 32, cp.async double buffer, 8 warps (2x4),
// warp tile 64x32 = 4x4 m16n8k8 tiles.
// head_layout=1 scatters C to [B,H,S,HD].
// ============================================================
#define GKC 32
#define GLDK 36                     /* padded row stride (floats) */
#define GTILE (128 * GLDK)          /* floats per buffer */
#define GEMM_SMEM (4 * GTILE * 4)   /* bytes: 2 bufs A + 2 bufs B */

__global__ __launch_bounds__(256, 2) void gemm_mma(
    const float* __restrict__ A, const float* __restrict__ Bt,
    const float* __restrict__ bias, float* __restrict__ Cout,
    int head_layout)
{
    extern __shared__ float sm[];
    float* As = sm;               // [2][128][GLDK]
    float* Bs = sm + 2 * GTILE;   // [2][128][GLDK]
    const uint32_t sa = smem_u32(As);
    const uint32_t sbb = smem_u32(Bs);

    const int tid = threadIdx.x;
    const int warp = tid >> 5;
    const int lane = tid & 31;
    const int grp = lane >> 2;     // 0..7
    const int tig = lane & 3;      // 0..3
    const int wm = (warp & 1) * 64;
    const int wn = (warp >> 1) * 32;
    const int bm = blockIdx.y * 128;
    const int bn = blockIdx.x * 128;

    // global->smem mapping: 1024 16B-segments per tile, 4 per thread
    const int lrow = tid >> 1;                 // unused-free mapping below
    (void)lrow;

    float acc[4][4][4];
#pragma unroll
    for (int mt = 0; mt < 4; mt++)
#pragma unroll
        for (int nt = 0; nt < 4; nt++)
#pragma unroll
            for (int i = 0; i < 4; i++) acc[mt][nt][i] = 0.0f;

    auto issue = [&](int chunk, int buf) {
        const int k0 = chunk * GKC;
#pragma unroll
        for (int i = 0; i < 4; i++) {
            const int s = tid + i * 256;       // 0..1023
            const int row = s >> 3;
            const int ks = (s & 7) * 4;
            const uint32_t soff = (uint32_t)(buf * GTILE + row * GLDK + ks) * 4u;
            cp_async16(sa + soff, A + (size_t)(bm + row) * D + k0 + ks);
            cp_async16(sbb + soff, Bt + (size_t)(bn + row) * D + k0 + ks);
        }
        CP_COMMIT();
    };

    issue(0, 0);

    const int NCHUNK = D / GKC;  // 32
    for (int c = 0; c < NCHUNK; c++) {
        const int buf = c & 1;
        if (c + 1 < NCHUNK) {
            issue(c + 1, 1 - buf);
            CP_WAIT(1);
        } else {
            CP_WAIT(0);
        }
        __syncthreads();

        const float* Ab = As + buf * GTILE;
        const float* Bb = Bs + buf * GTILE;
#pragma unroll
        for (int kk = 0; kk < 4; kk++) {
            const int k0 = kk * 8;
            uint32_t afr[4][4];
#pragma unroll
            for (int mt = 0; mt < 4; mt++) {
                const float* p = Ab + (wm + mt * 16 + grp) * GLDK + k0 + tig;
                afr[mt][0] = __float_as_uint(p[0]);
                afr[mt][1] = __float_as_uint(p[8 * GLDK]);
                afr[mt][2] = __float_as_uint(p[4]);
                afr[mt][3] = __float_as_uint(p[8 * GLDK + 4]);
            }
            uint32_t bfr[4][2];
#pragma unroll
            for (int nt = 0; nt < 4; nt++) {
                const float* p = Bb + (wn + nt * 8 + grp) * GLDK + k0 + tig;
                bfr[nt][0] = __float_as_uint(p[0]);
                bfr[nt][1] = __float_as_uint(p[4]);
            }
#pragma unroll
            for (int mt = 0; mt < 4; mt++)
#pragma unroll
                for (int nt = 0; nt < 4; nt++)
                    mma_tf32(acc[mt][nt], afr[mt], bfr[nt]);
        }
        __syncthreads();
    }

    // epilogue
#pragma unroll
    for (int mt = 0; mt < 4; mt++) {
#pragma unroll
        for (int nt = 0; nt < 4; nt++) {
            const int n = bn + wn + nt * 8 + 2 * tig;
            const float b0 = bias[n], b1 = bias[n + 1];
#pragma unroll
            for (int half = 0; half < 2; half++) {
                const int m = bm + wm + mt * 16 + grp + half * 8;
                float* dst;
                if (head_layout) {
                    const int bq = m >> 11;
                    const int s = m & (SEQ - 1);
                    const int h = n >> 6;
                    const int hd = n & (HDIM - 1);
                    dst = Cout + (((size_t)(bq * H + h)) * SEQ + s) * HDIM + hd;
                } else {
                    dst = Cout + (size_t)m * D + n;
                }
                float2 v;
                v.x = acc[mt][nt][half * 2 + 0] + b0;
                v.y = acc[mt][nt][half * 2 + 1] + b1;
                *reinterpret_cast<float2*>(dst) = v;
            }
        }
    }
}

// ============================================================
// Flash attention (fp32) — unchanged (proven R0)
// ============================================================
#define ABM 128
#define ABN 64
#define APAD 65

__global__ __launch_bounds__(256, 2) void attn_kernel(
    const float* __restrict__ Qg, const float* __restrict__ Kg,
    const float* __restrict__ Vg, float* __restrict__ ctx)
{
    extern __shared__ float smf[];
    float* Qs = smf;
    float* Ks = Qs + ABM * APAD;
    float* Vs = Ks + ABN * APAD;
    float* Ps = Vs + ABN * APAD;

    const int tid = threadIdx.x;
    const int tx = tid & 15;
    const int ty = tid >> 4;
    const int qt = blockIdx.x;
    const int bh = blockIdx.y;

    {
        const int r = tid >> 1;
        const int dbase = (tid & 1) * 32;
        const float inv = 0.125f;
        const float* src = Qg + ((size_t)bh * SEQ + qt * ABM + r) * HDIM + dbase;
        float* dst = Qs + r * APAD + dbase;
#pragma unroll
        for (int c = 0; c < 8; c++) {
            float4 v = *reinterpret_cast<const float4*>(src + c * 4);
            dst[c * 4 + 0] = v.x * inv;
            dst[c * 4 + 1] = v.y * inv;
            dst[c * 4 + 2] = v.z * inv;
            dst[c * 4 + 3] = v.w * inv;
        }
    }

    float m_i[8], l_i[8], o[8][4];
#pragma unroll
    for (int i = 0; i < 8; i++) {
        m_i[i] = -1e30f; l_i[i] = 0.0f;
#pragma unroll
        for (int j = 0; j < 4; j++) o[i][j] = 0.0f;
    }

    const float* Kbase = Kg + (size_t)bh * SEQ * HDIM;
    const float* Vbase = Vg + (size_t)bh * SEQ * HDIM;

    for (int kt = 0; kt < SEQ / ABN; kt++) {
        __syncthreads();
        {
            const int r = tid >> 2;
            const int dbase = (tid & 3) * 16;
            const float* ksrc = Kbase + ((size_t)kt * ABN + r) * HDIM + dbase;
            const float* vsrc = Vbase + ((size_t)kt * ABN + r) * HDIM + dbase;
            float* kdst = Ks + r * APAD + dbase;
            float* vdst = Vs + r * APAD + dbase;
#pragma unroll
            for (int c = 0; c < 4; c++) {
                float4 kv = *reinterpret_cast<const float4*>(ksrc + c * 4);
                kdst[c * 4 + 0] = kv.x; kdst[c * 4 + 1] = kv.y;
                kdst[c * 4 + 2] = kv.z; kdst[c * 4 + 3] = kv.w;
                float4 vv = *reinterpret_cast<const float4*>(vsrc + c * 4);
                vdst[c * 4 + 0] = vv.x; vdst[c * 4 + 1] = vv.y;
                vdst[c * 4 + 2] = vv.z; vdst[c * 4 + 3] = vv.w;
            }
        }
        __syncthreads();

        float s[8][4];
#pragma unroll
        for (int i = 0; i < 8; i++)
#pragma unroll
            for (int j = 0; j < 4; j++) s[i][j] = 0.0f;

        const float* qrow = Qs + ty * 8 * APAD;
        const float* kcol = Ks + tx * 4 * APAD;
#pragma unroll 8
        for (int d = 0; d < HDIM; d++) {
            float a[8], b[4];
#pragma unroll
            for (int i = 0; i < 8; i++) a[i] = qrow[i * APAD + d];
#pragma unroll
            for (int j = 0; j < 4; j++) b[j] = kcol[j * APAD + d];
#pragma unroll
            for (int i = 0; i < 8; i++)
#pragma unroll
                for (int j = 0; j < 4; j++) s[i][j] += a[i] * b[j];
        }

#pragma unroll
        for (int i = 0; i < 8; i++) {
            float mx = fmaxf(fmaxf(s[i][0], s[i][1]), fmaxf(s[i][2], s[i][3]));
            mx = fmaxf(mx, __shfl_xor_sync(0xffffffffu, mx, 1));
            mx = fmaxf(mx, __shfl_xor_sync(0xffffffffu, mx, 2));
            mx = fmaxf(mx, __shfl_xor_sync(0xffffffffu, mx, 4));
            mx = fmaxf(mx, __shfl_xor_sync(0xffffffffu, mx, 8));
            const float mnew = fmaxf(m_i[i], mx);
            float p[4]; float rs = 0.0f;
#pragma unroll
            for (int j = 0; j < 4; j++) { p[j] = __expf(s[i][j] - mnew); rs += p[j]; }
            rs += __shfl_xor_sync(0xffffffffu, rs, 1);
            rs += __shfl_xor_sync(0xffffffffu, rs, 2);
            rs += __shfl_xor_sync(0xffffffffu, rs, 4);
            rs += __shfl_xor_sync(0xffffffffu, rs, 8);
            const float corr = __expf(m_i[i] - mnew);
            l_i[i] = l_i[i] * corr + rs;
            m_i[i] = mnew;
#pragma unroll
            for (int j = 0; j < 4; j++) {
                o[i][j] *= corr;
                Ps[(ty * 8 + i) * APAD + tx * 4 + j] = p[j];
            }
        }
        __syncthreads();

        const float* prow = Ps + ty * 8 * APAD;
        const float* vcol = Vs + tx * 4;
#pragma unroll 8
        for (int kc = 0; kc < ABN; kc++) {
            float a[8], b[4];
#pragma unroll
            for (int i = 0; i < 8; i++) a[i] = prow[i * APAD + kc];
#pragma unroll
            for (int j = 0; j < 4; j++) b[j] = vcol[kc * APAD + j];
#pragma unroll
            for (int i = 0; i < 8; i++)
#pragma unroll
                for (int j = 0; j < 4; j++) o[i][j] += a[i] * b[j];
        }
    }

    const int bq = bh >> 4;
    const int h = bh & (H - 1);
#pragma unroll
    for (int i = 0; i < 8; i++) {
        const int srow = qt * ABM + ty * 8 + i;
        const float invl = 1.0f / l_i[i];
        float* dst = ctx + ((size_t)bq * SEQ + srow) * D + h * HDIM + tx * 4;
#pragma unroll
        for (int j = 0; j < 4; j++) dst[j] = o[i][j] * invl;
    }
}

// ============================================================
// Launch
// ============================================================
extern "C" void kernel_launch(void* const* d_in, const int* in_sizes, int n_in,
                              void* d_out, int out_size)
{
    const float* x  = (const float*)d_in[0];
    const float* Wq = (const float*)d_in[1];
    const float* bq = (const float*)d_in[2];
    const float* Wk = (const float*)d_in[3];
    const float* bk = (const float*)d_in[4];
    const float* Wv = (const float*)d_in[5];
    const float* bv = (const float*)d_in[6];
    const float* Wo = (const float*)d_in[7];
    const float* bo = (const float*)d_in[8];
    float* out = (float*)d_out;

    float *Qd, *Kd, *Vd, *Ctxd, *Wtd;
    cudaGetSymbolAddress((void**)&Qd, g_Q);
    cudaGetSymbolAddress((void**)&Kd, g_K);
    cudaGetSymbolAddress((void**)&Vd, g_V);
    cudaGetSymbolAddress((void**)&Ctxd, g_ctx);
    cudaGetSymbolAddress((void**)&Wtd, g_Wt);

    const dim3 tgrid(D / 32, D / 32);
    transpose_w<<<tgrid, dim3(32, 8)>>>(Wq, Wtd + 0 * D * D);
    transpose_w<<<tgrid, dim3(32, 8)>>>(Wk, Wtd + 1 * D * D);
    transpose_w<<<tgrid, dim3(32, 8)>>>(Wv, Wtd + 2 * D * D);
    transpose_w<<<tgrid, dim3(32, 8)>>>(Wo, Wtd + 3 * D * D);

    cudaFuncSetAttribute(gemm_mma, cudaFuncAttributeMaxDynamicSharedMemorySize, GEMM_SMEM);
    const dim3 ggrid(D / 128, MROWS / 128);  // (8, 32)
    gemm_mma<<<ggrid, 256, GEMM_SMEM>>>(x, Wtd + 0 * D * D, bq, Qd, 1);
    gemm_mma<<<ggrid, 256, GEMM_SMEM>>>(x, Wtd + 1 * D * D, bk, Kd, 1);
    gemm_mma<<<ggrid, 256, GEMM_SMEM>>>(x, Wtd + 2 * D * D, bv, Vd, 1);

    const int attn_smem = (ABM * APAD + 2 * ABN * APAD + ABM * APAD) * (int)sizeof(float);
    cudaFuncSetAttribute(attn_kernel, cudaFuncAttributeMaxDynamicSharedMemorySize, attn_smem);
    attn_kernel<<<dim3(SEQ / ABM, BATCH * H), 256, attn_smem>>>(Qd, Kd, Vd, Ctxd);

    gemm_mma<<<ggrid, 256, GEMM_SMEM>>>(Ctxd, Wtd + 3 * D * D, bo, out, 0);
}

// round 4
// speedup vs baseline: 3.5943x; 2.3560x over previous
#include <cuda_runtime.h>
#include <cstdint>

#define D 1024
#define H 16
#define HDIM 64
#define BATCH 2
#define SEQ 2048
#define MROWS (BATCH * SEQ) /* 4096 */

// ---------------- scratch (device globals; allocation-free) ----------------
__device__ float g_Q[BATCH * H * SEQ * HDIM];
__device__ float g_K[BATCH * H * SEQ * HDIM];
__device__ float g_V[BATCH * H * SEQ * HDIM];
__device__ float g_ctx[MROWS * D];
__device__ float g_Wt[4 * D * D];   // transposed (tf32-rounded) weights

// ---------------- helpers ----------------
__device__ __forceinline__ uint32_t smem_u32(const void* p) {
    uint32_t a;
    asm("{ .reg .u64 t; cvta.to.shared.u64 t, %1; cvt.u32.u64 %0, t; }"
        : "=r"(a) : "l"(p));
    return a;
}
__device__ __forceinline__ float tf32r(float x) {
    float r; asm("cvt.rna.tf32.f32 %0, %1;" : "=f"(r) : "f"(x)); return r;
}
__device__ __forceinline__ void cp_async16(uint32_t dst, const void* src) {
    asm volatile("cp.async.cg.shared.global [%0], [%1], 16;" :: "r"(dst), "l"(src));
}
#define CP_COMMIT() asm volatile("cp.async.commit_group;" ::: "memory")
#define CP_WAIT(n)  asm volatile("cp.async.wait_group %0;" :: "n"(n) : "memory")

__device__ __forceinline__ void mma_tf32(float* c, const uint32_t* a, const uint32_t* b) {
    asm volatile(
        "mma.sync.aligned.m16n8k8.row.col.f32.tf32.tf32.f32 "
        "{%0,%1,%2,%3}, {%4,%5,%6,%7}, {%8,%9}, {%0,%1,%2,%3};"
        : "+f"(c[0]), "+f"(c[1]), "+f"(c[2]), "+f"(c[3])
        : "r"(a[0]), "r"(a[1]), "r"(a[2]), "r"(a[3]), "r"(b[0]), "r"(b[1]));
}

// ============================================================
// Weight transpose: Wt[n][k] = tf32_rna(W[k][n])  (1024x1024)
// ============================================================
__global__ __launch_bounds__(256) void transpose_w(const float* __restrict__ W,
                                                   float* __restrict__ Wt) {
    __shared__ float t[32][33];
    const int bx = blockIdx.x * 32;   // n
    const int by = blockIdx.y * 32;   // k
    const int x = threadIdx.x;
    const int y = threadIdx.y;        // 0..7
#pragma unroll
    for (int i = 0; i < 4; i++)
        t[y + 8 * i][x] = tf32r(W[(size_t)(by + y + 8 * i) * D + bx + x]);
    __syncthreads();
#pragma unroll
    for (int i = 0; i < 4; i++)
        Wt[(size_t)(bx + y + 8 * i) * D + by + x] = t[x][y + 8 * i];
}

// ============================================================
// mma.sync tf32 GEMM (proven R3): C = A @ Wt^T + bias
// ============================================================
#define GKC 32
#define GLDK 36
#define GTILE (128 * GLDK)
#define GEMM_SMEM (4 * GTILE * 4)

__global__ __launch_bounds__(256, 2) void gemm_mma(
    const float* __restrict__ A, const float* __restrict__ Bt,
    const float* __restrict__ bias, float* __restrict__ Cout,
    int head_layout)
{
    extern __shared__ float sm[];
    float* As = sm;
    float* Bs = sm + 2 * GTILE;
    const uint32_t sa = smem_u32(As);
    const uint32_t sbb = smem_u32(Bs);

    const int tid = threadIdx.x;
    const int warp = tid >> 5;
    const int lane = tid & 31;
    const int grp = lane >> 2;
    const int tig = lane & 3;
    const int wm = (warp & 1) * 64;
    const int wn = (warp >> 1) * 32;
    const int bm = blockIdx.y * 128;
    const int bn = blockIdx.x * 128;

    float acc[4][4][4];
#pragma unroll
    for (int mt = 0; mt < 4; mt++)
#pragma unroll
        for (int nt = 0; nt < 4; nt++)
#pragma unroll
            for (int i = 0; i < 4; i++) acc[mt][nt][i] = 0.0f;

    auto issue = [&](int chunk, int buf) {
        const int k0 = chunk * GKC;
#pragma unroll
        for (int i = 0; i < 4; i++) {
            const int s = tid + i * 256;
            const int row = s >> 3;
            const int ks = (s & 7) * 4;
            const uint32_t soff = (uint32_t)(buf * GTILE + row * GLDK + ks) * 4u;
            cp_async16(sa + soff, A + (size_t)(bm + row) * D + k0 + ks);
            cp_async16(sbb + soff, Bt + (size_t)(bn + row) * D + k0 + ks);
        }
        CP_COMMIT();
    };

    issue(0, 0);

    const int NCHUNK = D / GKC;
    for (int c = 0; c < NCHUNK; c++) {
        const int buf = c & 1;
        if (c + 1 < NCHUNK) {
            issue(c + 1, 1 - buf);
            CP_WAIT(1);
        } else {
            CP_WAIT(0);
        }
        __syncthreads();

        const float* Ab = As + buf * GTILE;
        const float* Bb = Bs + buf * GTILE;
#pragma unroll
        for (int kk = 0; kk < 4; kk++) {
            const int k0 = kk * 8;
            uint32_t afr[4][4];
#pragma unroll
            for (int mt = 0; mt < 4; mt++) {
                const float* p = Ab + (wm + mt * 16 + grp) * GLDK + k0 + tig;
                afr[mt][0] = __float_as_uint(p[0]);
                afr[mt][1] = __float_as_uint(p[8 * GLDK]);
                afr[mt][2] = __float_as_uint(p[4]);
                afr[mt][3] = __float_as_uint(p[8 * GLDK + 4]);
            }
            uint32_t bfr[4][2];
#pragma unroll
            for (int nt = 0; nt < 4; nt++) {
                const float* p = Bb + (wn + nt * 8 + grp) * GLDK + k0 + tig;
                bfr[nt][0] = __float_as_uint(p[0]);
                bfr[nt][1] = __float_as_uint(p[4]);
            }
#pragma unroll
            for (int mt = 0; mt < 4; mt++)
#pragma unroll
                for (int nt = 0; nt < 4; nt++)
                    mma_tf32(acc[mt][nt], afr[mt], bfr[nt]);
        }
        __syncthreads();
    }

#pragma unroll
    for (int mt = 0; mt < 4; mt++) {
#pragma unroll
        for (int nt = 0; nt < 4; nt++) {
            const int n = bn + wn + nt * 8 + 2 * tig;
            const float b0 = bias[n], b1 = bias[n + 1];
#pragma unroll
            for (int half = 0; half < 2; half++) {
                const int m = bm + wm + mt * 16 + grp + half * 8;
                float* dst;
                if (head_layout) {
                    const int bq = m >> 11;
                    const int s = m & (SEQ - 1);
                    const int h = n >> 6;
                    const int hd = n & (HDIM - 1);
                    dst = Cout + (((size_t)(bq * H + h)) * SEQ + s) * HDIM + hd;
                } else {
                    dst = Cout + (size_t)m * D + n;
                }
                float2 v;
                v.x = acc[mt][nt][half * 2 + 0] + b0;
                v.y = acc[mt][nt][half * 2 + 1] + b1;
                *reinterpret_cast<float2*>(dst) = v;
            }
        }
    }
}

// ============================================================
// tf32 mma.sync flash attention
// CTA: 128 q-rows x one (b,h); 8 warps, each 16 rows x 64 cols.
// K-tiles of 64, double-buffered cp.async. Online softmax on
// fragments; P via smem (reusing Q buffer) for PV re-layout.
// ============================================================
#define NT_TILES (SEQ / 64)   /* 32 */
#define QPAD 68
#define KPAD 68
#define VPAD 72
#define ATT_SMEM ((128 * QPAD + 2 * 64 * KPAD + 2 * 64 * VPAD) * 4)

__global__ __launch_bounds__(256) void attn_mma(
    const float* __restrict__ Qg, const float* __restrict__ Kg,
    const float* __restrict__ Vg, float* __restrict__ ctx)
{
    extern __shared__ float sm[];
    float* QP = sm;                         // [128][QPAD] : Q, then P
    float* Ks = sm + 128 * QPAD;            // [2][64][KPAD]
    float* Vs = Ks + 2 * 64 * KPAD;         // [2][64][VPAD]
    const uint32_t sk = smem_u32(Ks);
    const uint32_t sv = smem_u32(Vs);

    const int tid = threadIdx.x;
    const int warp = tid >> 5;
    const int lane = tid & 31;
    const int grp = lane >> 2;      // 0..7
    const int tig = lane & 3;       // 0..3
    const int wm = warp * 16;
    const int qt = blockIdx.x;      // 0..15
    const int bh = blockIdx.y;      // 0..31

    const float* Qbase = Qg + ((size_t)bh * SEQ + qt * 128) * HDIM;
    const float* Kbase = Kg + (size_t)bh * SEQ * HDIM;
    const float* Vbase = Vg + (size_t)bh * SEQ * HDIM;

    // ---- Q -> smem (scaled by 1/8, RNA-rounded to tf32) ----
    {
#pragma unroll
        for (int i = 0; i < 8; i++) {
            const int s = tid + i * 256;     // 0..2047 float4 segs
            const int row = s >> 4;
            const int j = (s & 15) * 4;
            float4 v = *reinterpret_cast<const float4*>(Qbase + row * HDIM + j);
            float* d = QP + row * QPAD + j;
            d[0] = tf32r(v.x * 0.125f);
            d[1] = tf32r(v.y * 0.125f);
            d[2] = tf32r(v.z * 0.125f);
            d[3] = tf32r(v.w * 0.125f);
        }
    }

    auto issue_kv = [&](int kt, int b) {
        const float* ksrc = Kbase + (size_t)kt * 64 * HDIM;
        const float* vsrc = Vbase + (size_t)kt * 64 * HDIM;
#pragma unroll
        for (int i = 0; i < 4; i++) {
            const int s = tid + i * 256;   // 0..1023
            const int row = s >> 4;
            const int j = (s & 15) * 4;
            cp_async16(sk + (uint32_t)(b * 64 * KPAD + row * KPAD + j) * 4u,
                       ksrc + row * HDIM + j);
            cp_async16(sv + (uint32_t)(b * 64 * VPAD + row * VPAD + j) * 4u,
                       vsrc + row * HDIM + j);
        }
        CP_COMMIT();
    };

    issue_kv(0, 0);
    __syncthreads();

    // ---- Q fragments in registers (persist across all K-tiles) ----
    uint32_t qf[8][4];
#pragma unroll
    for (int kg = 0; kg < 8; kg++) {
        const float* p = QP + (wm + grp) * QPAD + kg * 8 + tig;
        qf[kg][0] = __float_as_uint(p[0]);
        qf[kg][1] = __float_as_uint(p[8 * QPAD]);
        qf[kg][2] = __float_as_uint(p[4]);
        qf[kg][3] = __float_as_uint(p[8 * QPAD + 4]);
    }

    float m0 = -1e30f, m1 = -1e30f, l0 = 0.0f, l1 = 0.0f;
    float oa[8][4];
#pragma unroll
    for (int nt = 0; nt < 8; nt++)
#pragma unroll
        for (int i = 0; i < 4; i++) oa[nt][i] = 0.0f;

    for (int kt = 0; kt < NT_TILES; kt++) {
        const int buf = kt & 1;
        CP_WAIT(0);
        __syncthreads();
        if (kt + 1 < NT_TILES) issue_kv(kt + 1, 1 - buf);

        // ---- S = Q @ K^T ----
        float sacc[8][4];
#pragma unroll
        for (int nt = 0; nt < 8; nt++)
#pragma unroll
            for (int i = 0; i < 4; i++) sacc[nt][i] = 0.0f;

        const float* Kb = Ks + buf * 64 * KPAD;
#pragma unroll
        for (int kg = 0; kg < 8; kg++) {
            uint32_t bf[8][2];
#pragma unroll
            for (int nt = 0; nt < 8; nt++) {
                const float* p = Kb + (nt * 8 + grp) * KPAD + kg * 8 + tig;
                bf[nt][0] = __float_as_uint(p[0]);
                bf[nt][1] = __float_as_uint(p[4]);
            }
#pragma unroll
            for (int nt = 0; nt < 8; nt++)
                mma_tf32(sacc[nt], qf[kg], bf[nt]);
        }

        // ---- online softmax on fragments ----
        float mx0 = -1e30f, mx1 = -1e30f;
#pragma unroll
        for (int nt = 0; nt < 8; nt++) {
            mx0 = fmaxf(mx0, fmaxf(sacc[nt][0], sacc[nt][1]));
            mx1 = fmaxf(mx1, fmaxf(sacc[nt][2], sacc[nt][3]));
        }
        mx0 = fmaxf(mx0, __shfl_xor_sync(0xffffffffu, mx0, 1));
        mx0 = fmaxf(mx0, __shfl_xor_sync(0xffffffffu, mx0, 2));
        mx1 = fmaxf(mx1, __shfl_xor_sync(0xffffffffu, mx1, 1));
        mx1 = fmaxf(mx1, __shfl_xor_sync(0xffffffffu, mx1, 2));
        const float mn0 = fmaxf(m0, mx0);
        const float mn1 = fmaxf(m1, mx1);
        const float c0 = __expf(m0 - mn0);
        const float c1 = __expf(m1 - mn1);
        m0 = mn0; m1 = mn1;

        __syncwarp();   // prior PV reads of P done before overwriting
        float s0 = 0.0f, s1 = 0.0f;
#pragma unroll
        for (int nt = 0; nt < 8; nt++) {
            float2 p0, p1;
            p0.x = tf32r(__expf(sacc[nt][0] - mn0));
            p0.y = tf32r(__expf(sacc[nt][1] - mn0));
            p1.x = tf32r(__expf(sacc[nt][2] - mn1));
            p1.y = tf32r(__expf(sacc[nt][3] - mn1));
            s0 += p0.x + p0.y;
            s1 += p1.x + p1.y;
            *reinterpret_cast<float2*>(QP + (wm + grp) * QPAD + nt * 8 + 2 * tig) = p0;
            *reinterpret_cast<float2*>(QP + (wm + grp + 8) * QPAD + nt * 8 + 2 * tig) = p1;
        }
        s0 += __shfl_xor_sync(0xffffffffu, s0, 1);
        s0 += __shfl_xor_sync(0xffffffffu, s0, 2);
        s1 += __shfl_xor_sync(0xffffffffu, s1, 1);
        s1 += __shfl_xor_sync(0xffffffffu, s1, 2);
        l0 = l0 * c0 + s0;
        l1 = l1 * c1 + s1;
#pragma unroll
        for (int nt = 0; nt < 8; nt++) {
            oa[nt][0] *= c0; oa[nt][1] *= c0;
            oa[nt][2] *= c1; oa[nt][3] *= c1;
        }
        __syncwarp();   // P visible to all lanes of this warp

        // ---- O += P @ V ----
        const float* Vb = Vs + buf * 64 * VPAD;
#pragma unroll
        for (int kg = 0; kg < 8; kg++) {
            uint32_t af[4];
            const float* pp = QP + (wm + grp) * QPAD + kg * 8 + tig;
            af[0] = __float_as_uint(pp[0]);
            af[1] = __float_as_uint(pp[8 * QPAD]);
            af[2] = __float_as_uint(pp[4]);
            af[3] = __float_as_uint(pp[8 * QPAD + 4]);
#pragma unroll
            for (int nt = 0; nt < 8; nt++) {
                uint32_t bf2[2];
                const float* vp = Vb + (kg * 8 + tig) * VPAD + nt * 8 + grp;
                bf2[0] = __float_as_uint(vp[0]);
                bf2[1] = __float_as_uint(vp[4 * VPAD]);
                mma_tf32(oa[nt], af, bf2);
            }
        }
    }

    // ---- epilogue: normalize, write ctx [B,S,D] ----
    const float il0 = 1.0f / l0;
    const float il1 = 1.0f / l1;
    const int bq = bh >> 4;
    const int h = bh & (H - 1);
    const int gr0 = qt * 128 + wm + grp;
#pragma unroll
    for (int nt = 0; nt < 8; nt++) {
        const int col = h * HDIM + nt * 8 + 2 * tig;
        float2 v0, v1;
        v0.x = oa[nt][0] * il0; v0.y = oa[nt][1] * il0;
        v1.x = oa[nt][2] * il1; v1.y = oa[nt][3] * il1;
        *reinterpret_cast<float2*>(ctx + ((size_t)bq * SEQ + gr0) * D + col) = v0;
        *reinterpret_cast<float2*>(ctx + ((size_t)bq * SEQ + gr0 + 8) * D + col) = v1;
    }
}

// ============================================================
// Launch
// ============================================================
extern "C" void kernel_launch(void* const* d_in, const int* in_sizes, int n_in,
                              void* d_out, int out_size)
{
    const float* x  = (const float*)d_in[0];
    const float* Wq = (const float*)d_in[1];
    const float* bq = (const float*)d_in[2];
    const float* Wk = (const float*)d_in[3];
    const float* bk = (const float*)d_in[4];
    const float* Wv = (const float*)d_in[5];
    const float* bv = (const float*)d_in[6];
    const float* Wo = (const float*)d_in[7];
    const float* bo = (const float*)d_in[8];
    float* out = (float*)d_out;

    float *Qd, *Kd, *Vd, *Ctxd, *Wtd;
    cudaGetSymbolAddress((void**)&Qd, g_Q);
    cudaGetSymbolAddress((void**)&Kd, g_K);
    cudaGetSymbolAddress((void**)&Vd, g_V);
    cudaGetSymbolAddress((void**)&Ctxd, g_ctx);
    cudaGetSymbolAddress((void**)&Wtd, g_Wt);

    const dim3 tgrid(D / 32, D / 32);
    transpose_w<<<tgrid, dim3(32, 8)>>>(Wq, Wtd + 0 * D * D);
    transpose_w<<<tgrid, dim3(32, 8)>>>(Wk, Wtd + 1 * D * D);
    transpose_w<<<tgrid, dim3(32, 8)>>>(Wv, Wtd + 2 * D * D);
    transpose_w<<<tgrid, dim3(32, 8)>>>(Wo, Wtd + 3 * D * D);

    cudaFuncSetAttribute(gemm_mma, cudaFuncAttributeMaxDynamicSharedMemorySize, GEMM_SMEM);
    const dim3 ggrid(D / 128, MROWS / 128);
    gemm_mma<<<ggrid, 256, GEMM_SMEM>>>(x, Wtd + 0 * D * D, bq, Qd, 1);
    gemm_mma<<<ggrid, 256, GEMM_SMEM>>>(x, Wtd + 1 * D * D, bk, Kd, 1);
    gemm_mma<<<ggrid, 256, GEMM_SMEM>>>(x, Wtd + 2 * D * D, bv, Vd, 1);

    cudaFuncSetAttribute(attn_mma, cudaFuncAttributeMaxDynamicSharedMemorySize, ATT_SMEM);
    attn_mma<<<dim3(SEQ / 128, BATCH * H), 256, ATT_SMEM>>>(Qd, Kd, Vd, Ctxd);

    gemm_mma<<<ggrid, 256, GEMM_SMEM>>>(Ctxd, Wtd + 3 * D * D, bo, out, 0);
}

// round 5
// speedup vs baseline: 3.6378x; 1.0121x over previous
#include <cuda_runtime.h>
#include <cstdint>

#define D 1024
#define H 16
#define HDIM 64
#define BATCH 2
#define SEQ 2048
#define MROWS (BATCH * SEQ) /* 4096 */

// ---------------- scratch (device globals; allocation-free) ----------------
__device__ float g_Q[BATCH * H * SEQ * HDIM];
__device__ float g_K[BATCH * H * SEQ * HDIM];
__device__ float g_V[BATCH * H * SEQ * HDIM];
__device__ float g_ctx[MROWS * D];
__device__ float g_xr[MROWS * D];   // RNA-rounded x
__device__ float g_Wt[4 * D * D];   // transposed (tf32-rounded) weights

// ---------------- helpers ----------------
__device__ __forceinline__ uint32_t smem_u32(const void* p) {
    uint32_t a;
    asm("{ .reg .u64 t; cvta.to.shared.u64 t, %1; cvt.u32.u64 %0, t; }"
        : "=r"(a) : "l"(p));
    return a;
}
__device__ __forceinline__ float tf32r(float x) {
    float r; asm("cvt.rna.tf32.f32 %0, %1;" : "=f"(r) : "f"(x)); return r;
}
__device__ __forceinline__ void cp_async16(uint32_t dst, const void* src) {
    asm volatile("cp.async.cg.shared.global [%0], [%1], 16;" :: "r"(dst), "l"(src));
}
#define CP_COMMIT() asm volatile("cp.async.commit_group;" ::: "memory")
#define CP_WAIT(n)  asm volatile("cp.async.wait_group %0;" :: "n"(n) : "memory")

__device__ __forceinline__ void mma_tf32(float* c, const uint32_t* a, const uint32_t* b) {
    asm volatile(
        "mma.sync.aligned.m16n8k8.row.col.f32.tf32.tf32.f32 "
        "{%0,%1,%2,%3}, {%4,%5,%6,%7}, {%8,%9}, {%0,%1,%2,%3};"
        : "+f"(c[0]), "+f"(c[1]), "+f"(c[2]), "+f"(c[3])
        : "r"(a[0]), "r"(a[1]), "r"(a[2]), "r"(a[3]), "r"(b[0]), "r"(b[1]));
}

// ============================================================
// Prep: RNA-round x into g_xr
// ============================================================
__global__ __launch_bounds__(256) void round_x(const float* __restrict__ x) {
    const int i = (blockIdx.x * 256 + threadIdx.x) * 4;
    float4 v = *reinterpret_cast<const float4*>(x + i);
    v.x = tf32r(v.x); v.y = tf32r(v.y); v.z = tf32r(v.z); v.w = tf32r(v.w);
    *reinterpret_cast<float4*>(g_xr + i) = v;
}

// ============================================================
// All 4 weight transposes in one launch: Wt[n][k] = tf32(W[k][n])
// blockIdx.z selects the weight.
// ============================================================
__global__ __launch_bounds__(256) void transpose_all(
    const float* __restrict__ W0, const float* __restrict__ W1,
    const float* __restrict__ W2, const float* __restrict__ W3) {
    __shared__ float t[32][33];
    const float* W = (blockIdx.z == 0) ? W0 : (blockIdx.z == 1) ? W1
                   : (blockIdx.z == 2) ? W2 : W3;
    float* Wt = g_Wt + (size_t)blockIdx.z * D * D;
    const int bx = blockIdx.x * 32;   // n
    const int by = blockIdx.y * 32;   // k
    const int x = threadIdx.x;
    const int y = threadIdx.y;        // 0..7
#pragma unroll
    for (int i = 0; i < 4; i++)
        t[y + 8 * i][x] = tf32r(W[(size_t)(by + y + 8 * i) * D + bx + x]);
    __syncthreads();
#pragma unroll
    for (int i = 0; i < 4; i++)
        Wt[(size_t)(bx + y + 8 * i) * D + by + x] = t[x][y + 8 * i];
}

// ============================================================
// mma.sync tf32 GEMM core (proven R3/R4)
// ============================================================
#define GKC 32
#define GLDK 36
#define GTILE (128 * GLDK)
#define GEMM_SMEM (4 * GTILE * 4)

struct GemmAcc { float a[4][4][4]; };

__device__ __forceinline__ void gemm_core(
    const float* __restrict__ A, const float* __restrict__ Bt,
    int bm, int bn, float* sm, GemmAcc& G)
{
    float* As = sm;
    float* Bs = sm + 2 * GTILE;
    const uint32_t sa = smem_u32(As);
    const uint32_t sbb = smem_u32(Bs);

    const int tid = threadIdx.x;
    const int warp = tid >> 5;
    const int lane = tid & 31;
    const int grp = lane >> 2;
    const int tig = lane & 3;
    const int wm = (warp & 1) * 64;
    const int wn = (warp >> 1) * 32;

#pragma unroll
    for (int mt = 0; mt < 4; mt++)
#pragma unroll
        for (int nt = 0; nt < 4; nt++)
#pragma unroll
            for (int i = 0; i < 4; i++) G.a[mt][nt][i] = 0.0f;

    auto issue = [&](int chunk, int buf) {
        const int k0 = chunk * GKC;
#pragma unroll
        for (int i = 0; i < 4; i++) {
            const int s = tid + i * 256;
            const int row = s >> 3;
            const int ks = (s & 7) * 4;
            const uint32_t soff = (uint32_t)(buf * GTILE + row * GLDK + ks) * 4u;
            cp_async16(sa + soff, A + (size_t)(bm + row) * D + k0 + ks);
            cp_async16(sbb + soff, Bt + (size_t)(bn + row) * D + k0 + ks);
        }
        CP_COMMIT();
    };

    issue(0, 0);

    const int NCHUNK = D / GKC;
    for (int c = 0; c < NCHUNK; c++) {
        const int buf = c & 1;
        if (c + 1 < NCHUNK) {
            issue(c + 1, 1 - buf);
            CP_WAIT(1);
        } else {
            CP_WAIT(0);
        }
        __syncthreads();

        const float* Ab = As + buf * GTILE;
        const float* Bb = Bs + buf * GTILE;
#pragma unroll
        for (int kk = 0; kk < 4; kk++) {
            const int k0 = kk * 8;
            uint32_t afr[4][4];
#pragma unroll
            for (int mt = 0; mt < 4; mt++) {
                const float* p = Ab + (wm + mt * 16 + grp) * GLDK + k0 + tig;
                afr[mt][0] = __float_as_uint(p[0]);
                afr[mt][1] = __float_as_uint(p[8 * GLDK]);
                afr[mt][2] = __float_as_uint(p[4]);
                afr[mt][3] = __float_as_uint(p[8 * GLDK + 4]);
            }
            uint32_t bfr[4][2];
#pragma unroll
            for (int nt = 0; nt < 4; nt++) {
                const float* p = Bb + (wn + nt * 8 + grp) * GLDK + k0 + tig;
                bfr[nt][0] = __float_as_uint(p[0]);
                bfr[nt][1] = __float_as_uint(p[4]);
            }
#pragma unroll
            for (int mt = 0; mt < 4; mt++)
#pragma unroll
                for (int nt = 0; nt < 4; nt++)
                    mma_tf32(G.a[mt][nt], afr[mt], bfr[nt]);
        }
        __syncthreads();
    }
}

// ---- merged QKV projection: grid (24, 32). sector = bx/8 -> Q/K/V ----
__global__ __launch_bounds__(256, 2) void qkv_gemm(
    const float* __restrict__ xr,
    const float* __restrict__ bqv, const float* __restrict__ bkv,
    const float* __restrict__ bvv)
{
    extern __shared__ float sm[];
    const int sector = blockIdx.x >> 3;           // 0,1,2
    const int bn = (blockIdx.x & 7) * 128;
    const int bm = blockIdx.y * 128;
    const float* Bt = g_Wt + (size_t)sector * D * D;
    const float* bias = (sector == 0) ? bqv : (sector == 1) ? bkv : bvv;
    float* outp = (sector == 0) ? g_Q : (sector == 1) ? g_K : g_V;

    GemmAcc G;
    gemm_core(xr, Bt, bm, bn, sm, G);

    const int tid = threadIdx.x;
    const int warp = tid >> 5;
    const int lane = tid & 31;
    const int grp = lane >> 2;
    const int tig = lane & 3;
    const int wm = (warp & 1) * 64;
    const int wn = (warp >> 1) * 32;

#pragma unroll
    for (int mt = 0; mt < 4; mt++) {
#pragma unroll
        for (int nt = 0; nt < 4; nt++) {
            const int n = bn + wn + nt * 8 + 2 * tig;
            const float b0 = bias[n], b1 = bias[n + 1];
#pragma unroll
            for (int half = 0; half < 2; half++) {
                const int m = bm + wm + mt * 16 + grp + half * 8;
                const int bq = m >> 11;
                const int s = m & (SEQ - 1);
                const int h = n >> 6;
                const int hd = n & (HDIM - 1);
                float2 v;
                v.x = tf32r(G.a[mt][nt][half * 2 + 0] + b0);
                v.y = tf32r(G.a[mt][nt][half * 2 + 1] + b1);
                *reinterpret_cast<float2*>(
                    outp + (((size_t)(bq * H + h)) * SEQ + s) * HDIM + hd) = v;
            }
        }
    }
}

// ---- O projection: plain layout, no rounding ----
__global__ __launch_bounds__(256, 2) void o_gemm(
    const float* __restrict__ A, const float* __restrict__ Bt,
    const float* __restrict__ bias, float* __restrict__ Cout)
{
    extern __shared__ float sm[];
    const int bn = blockIdx.x * 128;
    const int bm = blockIdx.y * 128;

    GemmAcc G;
    gemm_core(A, Bt, bm, bn, sm, G);

    const int tid = threadIdx.x;
    const int warp = tid >> 5;
    const int lane = tid & 31;
    const int grp = lane >> 2;
    const int tig = lane & 3;
    const int wm = (warp & 1) * 64;
    const int wn = (warp >> 1) * 32;

#pragma unroll
    for (int mt = 0; mt < 4; mt++) {
#pragma unroll
        for (int nt = 0; nt < 4; nt++) {
            const int n = bn + wn + nt * 8 + 2 * tig;
            const float b0 = bias[n], b1 = bias[n + 1];
#pragma unroll
            for (int half = 0; half < 2; half++) {
                const int m = bm + wm + mt * 16 + grp + half * 8;
                float2 v;
                v.x = G.a[mt][nt][half * 2 + 0] + b0;
                v.y = G.a[mt][nt][half * 2 + 1] + b1;
                *reinterpret_cast<float2*>(Cout + (size_t)m * D + n) = v;
            }
        }
    }
}

// ============================================================
// tf32 mma.sync flash attention (proven R4) + RNA-rounded ctx
// ============================================================
#define NT_TILES (SEQ / 64)   /* 32 */
#define QPAD 68
#define KPAD 68
#define VPAD 72
#define ATT_SMEM ((128 * QPAD + 2 * 64 * KPAD + 2 * 64 * VPAD) * 4)

__global__ __launch_bounds__(256) void attn_mma(
    const float* __restrict__ Qg, const float* __restrict__ Kg,
    const float* __restrict__ Vg, float* __restrict__ ctx)
{
    extern __shared__ float sm[];
    float* QP = sm;                         // [128][QPAD] : Q, then P
    float* Ks = sm + 128 * QPAD;            // [2][64][KPAD]
    float* Vs = Ks + 2 * 64 * KPAD;         // [2][64][VPAD]
    const uint32_t sk = smem_u32(Ks);
    const uint32_t sv = smem_u32(Vs);

    const int tid = threadIdx.x;
    const int warp = tid >> 5;
    const int lane = tid & 31;
    const int grp = lane >> 2;      // 0..7
    const int tig = lane & 3;       // 0..3
    const int wm = warp * 16;
    const int qt = blockIdx.x;      // 0..15
    const int bh = blockIdx.y;      // 0..31

    const float* Qbase = Qg + ((size_t)bh * SEQ + qt * 128) * HDIM;
    const float* Kbase = Kg + (size_t)bh * SEQ * HDIM;
    const float* Vbase = Vg + (size_t)bh * SEQ * HDIM;

    // ---- Q -> smem (scaled by 1/8; inputs already tf32-rounded) ----
    {
#pragma unroll
        for (int i = 0; i < 8; i++) {
            const int s = tid + i * 256;
            const int row = s >> 4;
            const int j = (s & 15) * 4;
            float4 v = *reinterpret_cast<const float4*>(Qbase + row * HDIM + j);
            float* d = QP + row * QPAD + j;
            d[0] = v.x * 0.125f;
            d[1] = v.y * 0.125f;
            d[2] = v.z * 0.125f;
            d[3] = v.w * 0.125f;
        }
    }

    auto issue_kv = [&](int kt, int b) {
        const float* ksrc = Kbase + (size_t)kt * 64 * HDIM;
        const float* vsrc = Vbase + (size_t)kt * 64 * HDIM;
#pragma unroll
        for (int i = 0; i < 4; i++) {
            const int s = tid + i * 256;
            const int row = s >> 4;
            const int j = (s & 15) * 4;
            cp_async16(sk + (uint32_t)(b * 64 * KPAD + row * KPAD + j) * 4u,
                       ksrc + row * HDIM + j);
            cp_async16(sv + (uint32_t)(b * 64 * VPAD + row * VPAD + j) * 4u,
                       vsrc + row * HDIM + j);
        }
        CP_COMMIT();
    };

    issue_kv(0, 0);
    __syncthreads();

    uint32_t qf[8][4];
#pragma unroll
    for (int kg = 0; kg < 8; kg++) {
        const float* p = QP + (wm + grp) * QPAD + kg * 8 + tig;
        qf[kg][0] = __float_as_uint(p[0]);
        qf[kg][1] = __float_as_uint(p[8 * QPAD]);
        qf[kg][2] = __float_as_uint(p[4]);
        qf[kg][3] = __float_as_uint(p[8 * QPAD + 4]);
    }

    float m0 = -1e30f, m1 = -1e30f, l0 = 0.0f, l1 = 0.0f;
    float oa[8][4];
#pragma unroll
    for (int nt = 0; nt < 8; nt++)
#pragma unroll
        for (int i = 0; i < 4; i++) oa[nt][i] = 0.0f;

    for (int kt = 0; kt < NT_TILES; kt++) {
        const int buf = kt & 1;
        CP_WAIT(0);
        __syncthreads();
        if (kt + 1 < NT_TILES) issue_kv(kt + 1, 1 - buf);

        // ---- S = Q @ K^T ----
        float sacc[8][4];
#pragma unroll
        for (int nt = 0; nt < 8; nt++)
#pragma unroll
            for (int i = 0; i < 4; i++) sacc[nt][i] = 0.0f;

        const float* Kb = Ks + buf * 64 * KPAD;
#pragma unroll
        for (int kg = 0; kg < 8; kg++) {
            uint32_t bf[8][2];
#pragma unroll
            for (int nt = 0; nt < 8; nt++) {
                const float* p = Kb + (nt * 8 + grp) * KPAD + kg * 8 + tig;
                bf[nt][0] = __float_as_uint(p[0]);
                bf[nt][1] = __float_as_uint(p[4]);
            }
#pragma unroll
            for (int nt = 0; nt < 8; nt++)
                mma_tf32(sacc[nt], qf[kg], bf[nt]);
        }

        // ---- online softmax ----
        float mx0 = -1e30f, mx1 = -1e30f;
#pragma unroll
        for (int nt = 0; nt < 8; nt++) {
            mx0 = fmaxf(mx0, fmaxf(sacc[nt][0], sacc[nt][1]));
            mx1 = fmaxf(mx1, fmaxf(sacc[nt][2], sacc[nt][3]));
        }
        mx0 = fmaxf(mx0, __shfl_xor_sync(0xffffffffu, mx0, 1));
        mx0 = fmaxf(mx0, __shfl_xor_sync(0xffffffffu, mx0, 2));
        mx1 = fmaxf(mx1, __shfl_xor_sync(0xffffffffu, mx1, 1));
        mx1 = fmaxf(mx1, __shfl_xor_sync(0xffffffffu, mx1, 2));
        const float mn0 = fmaxf(m0, mx0);
        const float mn1 = fmaxf(m1, mx1);
        const float c0 = __expf(m0 - mn0);
        const float c1 = __expf(m1 - mn1);
        m0 = mn0; m1 = mn1;

        __syncwarp();
        float s0 = 0.0f, s1 = 0.0f;
#pragma unroll
        for (int nt = 0; nt < 8; nt++) {
            float2 p0, p1;
            p0.x = tf32r(__expf(sacc[nt][0] - mn0));
            p0.y = tf32r(__expf(sacc[nt][1] - mn0));
            p1.x = tf32r(__expf(sacc[nt][2] - mn1));
            p1.y = tf32r(__expf(sacc[nt][3] - mn1));
            s0 += p0.x + p0.y;
            s1 += p1.x + p1.y;
            *reinterpret_cast<float2*>(QP + (wm + grp) * QPAD + nt * 8 + 2 * tig) = p0;
            *reinterpret_cast<float2*>(QP + (wm + grp + 8) * QPAD + nt * 8 + 2 * tig) = p1;
        }
        s0 += __shfl_xor_sync(0xffffffffu, s0, 1);
        s0 += __shfl_xor_sync(0xffffffffu, s0, 2);
        s1 += __shfl_xor_sync(0xffffffffu, s1, 1);
        s1 += __shfl_xor_sync(0xffffffffu, s1, 2);
        l0 = l0 * c0 + s0;
        l1 = l1 * c1 + s1;
#pragma unroll
        for (int nt = 0; nt < 8; nt++) {
            oa[nt][0] *= c0; oa[nt][1] *= c0;
            oa[nt][2] *= c1; oa[nt][3] *= c1;
        }
        __syncwarp();

        // ---- O += P @ V ----
        const float* Vb = Vs + buf * 64 * VPAD;
#pragma unroll
        for (int kg = 0; kg < 8; kg++) {
            uint32_t af[4];
            const float* pp = QP + (wm + grp) * QPAD + kg * 8 + tig;
            af[0] = __float_as_uint(pp[0]);
            af[1] = __float_as_uint(pp[8 * QPAD]);
            af[2] = __float_as_uint(pp[4]);
            af[3] = __float_as_uint(pp[8 * QPAD + 4]);
#pragma unroll
            for (int nt = 0; nt < 8; nt++) {
                uint32_t bf2[2];
                const float* vp = Vb + (kg * 8 + tig) * VPAD + nt * 8 + grp;
                bf2[0] = __float_as_uint(vp[0]);
                bf2[1] = __float_as_uint(vp[4 * VPAD]);
                mma_tf32(oa[nt], af, bf2);
            }
        }
    }

    // ---- epilogue: normalize, RNA-round, write ctx [B,S,D] ----
    const float il0 = 1.0f / l0;
    const float il1 = 1.0f / l1;
    const int bq = bh >> 4;
    const int h = bh & (H - 1);
    const int gr0 = qt * 128 + wm + grp;
#pragma unroll
    for (int nt = 0; nt < 8; nt++) {
        const int col = h * HDIM + nt * 8 + 2 * tig;
        float2 v0, v1;
        v0.x = tf32r(oa[nt][0] * il0); v0.y = tf32r(oa[nt][1] * il0);
        v1.x = tf32r(oa[nt][2] * il1); v1.y = tf32r(oa[nt][3] * il1);
        *reinterpret_cast<float2*>(ctx + ((size_t)bq * SEQ + gr0) * D + col) = v0;
        *reinterpret_cast<float2*>(ctx + ((size_t)bq * SEQ + gr0 + 8) * D + col) = v1;
    }
}

// ============================================================
// Launch
// ============================================================
extern "C" void kernel_launch(void* const* d_in, const int* in_sizes, int n_in,
                              void* d_out, int out_size)
{
    const float* x  = (const float*)d_in[0];
    const float* Wq = (const float*)d_in[1];
    const float* bq = (const float*)d_in[2];
    const float* Wk = (const float*)d_in[3];
    const float* bk = (const float*)d_in[4];
    const float* Wv = (const float*)d_in[5];
    const float* bv = (const float*)d_in[6];
    const float* Wo = (const float*)d_in[7];
    const float* bo = (const float*)d_in[8];
    float* out = (float*)d_out;

    float *Qd, *Kd, *Vd, *Ctxd, *Wtd, *xrd;
    cudaGetSymbolAddress((void**)&Qd, g_Q);
    cudaGetSymbolAddress((void**)&Kd, g_K);
    cudaGetSymbolAddress((void**)&Vd, g_V);
    cudaGetSymbolAddress((void**)&Ctxd, g_ctx);
    cudaGetSymbolAddress((void**)&Wtd, g_Wt);
    cudaGetSymbolAddress((void**)&xrd, g_xr);

    round_x<<<MROWS * D / 1024, 256>>>(x);
    transpose_all<<<dim3(D / 32, D / 32, 4), dim3(32, 8)>>>(Wq, Wk, Wv, Wo);

    cudaFuncSetAttribute(qkv_gemm, cudaFuncAttributeMaxDynamicSharedMemorySize, GEMM_SMEM);
    cudaFuncSetAttribute(o_gemm, cudaFuncAttributeMaxDynamicSharedMemorySize, GEMM_SMEM);
    qkv_gemm<<<dim3(24, MROWS / 128), 256, GEMM_SMEM>>>(xrd, bq, bk, bv);

    cudaFuncSetAttribute(attn_mma, cudaFuncAttributeMaxDynamicSharedMemorySize, ATT_SMEM);
    attn_mma<<<dim3(SEQ / 128, BATCH * H), 256, ATT_SMEM>>>(Qd, Kd, Vd, Ctxd);

    o_gemm<<<dim3(D / 128, MROWS / 128), 256, GEMM_SMEM>>>(Ctxd, Wtd + 3 * (size_t)D * D, bo, out);
}

// round 6
// speedup vs baseline: 4.7198x; 1.2974x over previous
#include <cuda_runtime.h>
#include <cuda_fp16.h>
#include <cstdint>

#define D 1024
#define H 16
#define HDIM 64
#define BATCH 2
#define SEQ 2048
#define MROWS (BATCH * SEQ) /* 4096 */

// ---------------- scratch (device globals; allocation-free) ----------------
__device__ __half g_Qh[BATCH * H * SEQ * HDIM];          // [bh][s][d], pre-scaled 1/8
__device__ __half g_Kh[BATCH * H * SEQ * HDIM];          // [bh][s][d]
__device__ __half g_Vth[BATCH * H * HDIM * SEQ];         // [bh][d][s]  (V transposed)
__device__ float g_ctx[MROWS * D];
__device__ float g_xr[MROWS * D];   // RNA-rounded x
__device__ float g_Wt[4 * D * D];   // transposed (tf32-rounded) weights

// ---------------- helpers ----------------
__device__ __forceinline__ uint32_t smem_u32(const void* p) {
    uint32_t a;
    asm("{ .reg .u64 t; cvta.to.shared.u64 t, %1; cvt.u32.u64 %0, t; }"
        : "=r"(a) : "l"(p));
    return a;
}
__device__ __forceinline__ float tf32r(float x) {
    float r; asm("cvt.rna.tf32.f32 %0, %1;" : "=f"(r) : "f"(x)); return r;
}
__device__ __forceinline__ void cp_async16(uint32_t dst, const void* src) {
    asm volatile("cp.async.cg.shared.global [%0], [%1], 16;" :: "r"(dst), "l"(src));
}
#define CP_COMMIT() asm volatile("cp.async.commit_group;" ::: "memory")
#define CP_WAIT(n)  asm volatile("cp.async.wait_group %0;" :: "n"(n) : "memory")

__device__ __forceinline__ void mma_tf32(float* c, const uint32_t* a, const uint32_t* b) {
    asm volatile(
        "mma.sync.aligned.m16n8k8.row.col.f32.tf32.tf32.f32 "
        "{%0,%1,%2,%3}, {%4,%5,%6,%7}, {%8,%9}, {%0,%1,%2,%3};"
        : "+f"(c[0]), "+f"(c[1]), "+f"(c[2]), "+f"(c[3])
        : "r"(a[0]), "r"(a[1]), "r"(a[2]), "r"(a[3]), "r"(b[0]), "r"(b[1]));
}
__device__ __forceinline__ void mma_f16(float* c, const uint32_t* a, const uint32_t* b) {
    asm volatile(
        "mma.sync.aligned.m16n8k16.row.col.f32.f16.f16.f32 "
        "{%0,%1,%2,%3}, {%4,%5,%6,%7}, {%8,%9}, {%0,%1,%2,%3};"
        : "+f"(c[0]), "+f"(c[1]), "+f"(c[2]), "+f"(c[3])
        : "r"(a[0]), "r"(a[1]), "r"(a[2]), "r"(a[3]), "r"(b[0]), "r"(b[1]));
}

// ============================================================
// Prep: RNA-round x into g_xr
// ============================================================
__global__ __launch_bounds__(256) void round_x(const float* __restrict__ x) {
    const int i = (blockIdx.x * 256 + threadIdx.x) * 4;
    float4 v = *reinterpret_cast<const float4*>(x + i);
    v.x = tf32r(v.x); v.y = tf32r(v.y); v.z = tf32r(v.z); v.w = tf32r(v.w);
    *reinterpret_cast<float4*>(g_xr + i) = v;
}

// ============================================================
// All 4 weight transposes in one launch
// ============================================================
__global__ __launch_bounds__(256) void transpose_all(
    const float* __restrict__ W0, const float* __restrict__ W1,
    const float* __restrict__ W2, const float* __restrict__ W3) {
    __shared__ float t[32][33];
    const float* W = (blockIdx.z == 0) ? W0 : (blockIdx.z == 1) ? W1
                   : (blockIdx.z == 2) ? W2 : W3;
    float* Wt = g_Wt + (size_t)blockIdx.z * D * D;
    const int bx = blockIdx.x * 32;
    const int by = blockIdx.y * 32;
    const int x = threadIdx.x;
    const int y = threadIdx.y;
#pragma unroll
    for (int i = 0; i < 4; i++)
        t[y + 8 * i][x] = tf32r(W[(size_t)(by + y + 8 * i) * D + bx + x]);
    __syncthreads();
#pragma unroll
    for (int i = 0; i < 4; i++)
        Wt[(size_t)(bx + y + 8 * i) * D + by + x] = t[x][y + 8 * i];
}

// ============================================================
// mma.sync tf32 GEMM core (proven)
// ============================================================
#define GKC 32
#define GLDK 36
#define GTILE (128 * GLDK)
#define GEMM_SMEM (4 * GTILE * 4)

struct GemmAcc { float a[4][4][4]; };

__device__ __forceinline__ void gemm_core(
    const float* __restrict__ A, const float* __restrict__ Bt,
    int bm, int bn, float* sm, GemmAcc& G)
{
    float* As = sm;
    float* Bs = sm + 2 * GTILE;
    const uint32_t sa = smem_u32(As);
    const uint32_t sbb = smem_u32(Bs);

    const int tid = threadIdx.x;
    const int warp = tid >> 5;
    const int lane = tid & 31;
    const int grp = lane >> 2;
    const int tig = lane & 3;
    const int wm = (warp & 1) * 64;
    const int wn = (warp >> 1) * 32;

#pragma unroll
    for (int mt = 0; mt < 4; mt++)
#pragma unroll
        for (int nt = 0; nt < 4; nt++)
#pragma unroll
            for (int i = 0; i < 4; i++) G.a[mt][nt][i] = 0.0f;

    auto issue = [&](int chunk, int buf) {
        const int k0 = chunk * GKC;
#pragma unroll
        for (int i = 0; i < 4; i++) {
            const int s = tid + i * 256;
            const int row = s >> 3;
            const int ks = (s & 7) * 4;
            const uint32_t soff = (uint32_t)(buf * GTILE + row * GLDK + ks) * 4u;
            cp_async16(sa + soff, A + (size_t)(bm + row) * D + k0 + ks);
            cp_async16(sbb + soff, Bt + (size_t)(bn + row) * D + k0 + ks);
        }
        CP_COMMIT();
    };

    issue(0, 0);

    const int NCHUNK = D / GKC;
    for (int c = 0; c < NCHUNK; c++) {
        const int buf = c & 1;
        if (c + 1 < NCHUNK) {
            issue(c + 1, 1 - buf);
            CP_WAIT(1);
        } else {
            CP_WAIT(0);
        }
        __syncthreads();

        const float* Ab = As + buf * GTILE;
        const float* Bb = Bs + buf * GTILE;
#pragma unroll
        for (int kk = 0; kk < 4; kk++) {
            const int k0 = kk * 8;
            uint32_t afr[4][4];
#pragma unroll
            for (int mt = 0; mt < 4; mt++) {
                const float* p = Ab + (wm + mt * 16 + grp) * GLDK + k0 + tig;
                afr[mt][0] = __float_as_uint(p[0]);
                afr[mt][1] = __float_as_uint(p[8 * GLDK]);
                afr[mt][2] = __float_as_uint(p[4]);
                afr[mt][3] = __float_as_uint(p[8 * GLDK + 4]);
            }
            uint32_t bfr[4][2];
#pragma unroll
            for (int nt = 0; nt < 4; nt++) {
                const float* p = Bb + (wn + nt * 8 + grp) * GLDK + k0 + tig;
                bfr[nt][0] = __float_as_uint(p[0]);
                bfr[nt][1] = __float_as_uint(p[4]);
            }
#pragma unroll
            for (int mt = 0; mt < 4; mt++)
#pragma unroll
                for (int nt = 0; nt < 4; nt++)
                    mma_tf32(G.a[mt][nt], afr[mt], bfr[nt]);
        }
        __syncthreads();
    }
}

// ---- merged QKV projection: grid (24, 32); emits half Q/K, half V^T ----
__global__ __launch_bounds__(256, 2) void qkv_gemm(
    const float* __restrict__ xr,
    const float* __restrict__ bqv, const float* __restrict__ bkv,
    const float* __restrict__ bvv)
{
    extern __shared__ float sm[];
    const int sector = blockIdx.x >> 3;           // 0=Q,1=K,2=V
    const int bn = (blockIdx.x & 7) * 128;
    const int bm = blockIdx.y * 128;
    const float* Bt = g_Wt + (size_t)sector * D * D;
    const float* bias = (sector == 0) ? bqv : (sector == 1) ? bkv : bvv;

    GemmAcc G;
    gemm_core(xr, Bt, bm, bn, sm, G);

    const int tid = threadIdx.x;
    const int warp = tid >> 5;
    const int lane = tid & 31;
    const int grp = lane >> 2;
    const int tig = lane & 3;
    const int wm = (warp & 1) * 64;
    const int wn = (warp >> 1) * 32;

#pragma unroll
    for (int mt = 0; mt < 4; mt++) {
#pragma unroll
        for (int nt = 0; nt < 4; nt++) {
            const int n = bn + wn + nt * 8 + 2 * tig;
            const float b0 = bias[n], b1 = bias[n + 1];
#pragma unroll
            for (int half = 0; half < 2; half++) {
                const int m = bm + wm + mt * 16 + grp + half * 8;
                const int bq = m >> 11;
                const int s = m & (SEQ - 1);
                const int h = n >> 6;
                const int hd = n & (HDIM - 1);
                const int bh = bq * H + h;
                float vx = G.a[mt][nt][half * 2 + 0] + b0;
                float vy = G.a[mt][nt][half * 2 + 1] + b1;
                if (sector == 0) {
                    __half2 hv = __floats2half2_rn(vx * 0.125f, vy * 0.125f);
                    *reinterpret_cast<__half2*>(
                        g_Qh + ((size_t)bh * SEQ + s) * HDIM + hd) = hv;
                } else if (sector == 1) {
                    __half2 hv = __floats2half2_rn(vx, vy);
                    *reinterpret_cast<__half2*>(
                        g_Kh + ((size_t)bh * SEQ + s) * HDIM + hd) = hv;
                } else {
                    g_Vth[((size_t)bh * HDIM + hd) * SEQ + s] = __float2half_rn(vx);
                    g_Vth[((size_t)bh * HDIM + hd + 1) * SEQ + s] = __float2half_rn(vy);
                }
            }
        }
    }
}

// ---- O projection: plain layout ----
__global__ __launch_bounds__(256, 2) void o_gemm(
    const float* __restrict__ A, const float* __restrict__ Bt,
    const float* __restrict__ bias, float* __restrict__ Cout)
{
    extern __shared__ float sm[];
    const int bn = blockIdx.x * 128;
    const int bm = blockIdx.y * 128;

    GemmAcc G;
    gemm_core(A, Bt, bm, bn, sm, G);

    const int tid = threadIdx.x;
    const int warp = tid >> 5;
    const int lane = tid & 31;
    const int grp = lane >> 2;
    const int tig = lane & 3;
    const int wm = (warp & 1) * 64;
    const int wn = (warp >> 1) * 32;

#pragma unroll
    for (int mt = 0; mt < 4; mt++) {
#pragma unroll
        for (int nt = 0; nt < 4; nt++) {
            const int n = bn + wn + nt * 8 + 2 * tig;
            const float b0 = bias[n], b1 = bias[n + 1];
#pragma unroll
            for (int half = 0; half < 2; half++) {
                const int m = bm + wm + mt * 16 + grp + half * 8;
                float2 v;
                v.x = G.a[mt][nt][half * 2 + 0] + b0;
                v.y = G.a[mt][nt][half * 2 + 1] + b1;
                *reinterpret_cast<float2*>(Cout + (size_t)m * D + n) = v;
            }
        }
    }
}

// ============================================================
// fp16 mma.sync flash attention (m16n8k16, f32 accum)
// CTA: 128 q-rows x one (b,h); 8 warps x (16 rows x 64 cols).
// smem (halves, stride 72): QP[128] | Ks[2][64] | Vts[2][64]
// ============================================================
#define NT_TILES (SEQ / 64)   /* 32 */
#define ALD 72                /* half stride per row */
#define QP_OFF 0
#define KS_OFF (128 * ALD)               /* 9216 */
#define VS_OFF (KS_OFF + 2 * 64 * ALD)   /* 18432 */
#define ATT_SMEM ((VS_OFF + 2 * 64 * ALD) * 2)  /* 55296 bytes */

__global__ __launch_bounds__(256, 2) void attn_mma(
    const __half* __restrict__ Qg, const __half* __restrict__ Kg,
    const __half* __restrict__ Vtg, float* __restrict__ ctx)
{
    extern __shared__ __half smh[];
    __half* QP = smh + QP_OFF;
    const uint32_t sbase = smem_u32(smh);

    const int tid = threadIdx.x;
    const int warp = tid >> 5;
    const int lane = tid & 31;
    const int grp = lane >> 2;      // 0..7
    const int tig = lane & 3;       // 0..3
    const int wm = warp * 16;
    const int qt = blockIdx.x;      // 0..15
    const int bh = blockIdx.y;      // 0..31

    const __half* Qbase = Qg + ((size_t)bh * SEQ + qt * 128) * HDIM;
    const __half* Kbase = Kg + (size_t)bh * SEQ * HDIM;
    const __half* Vtbase = Vtg + (size_t)bh * HDIM * SEQ;

    // ---- Q -> smem via cp.async (128 rows x 8 chunks of 16B) ----
#pragma unroll
    for (int i = 0; i < 4; i++) {
        const int s = tid + i * 256;          // 0..1023
        const int row = s >> 3;
        const int ch = s & 7;
        cp_async16(sbase + (uint32_t)(QP_OFF + row * ALD + ch * 8) * 2u,
                   Qbase + row * HDIM + ch * 8);
    }
    CP_COMMIT();

    auto issue_kv = [&](int kt, int b) {
        const __half* ksrc = Kbase + (size_t)kt * 64 * HDIM;
        const __half* vsrc = Vtbase + kt * 64;
#pragma unroll
        for (int i = 0; i < 2; i++) {
            const int s = tid + i * 256;      // 0..511
            const int row = s >> 3;
            const int ch = s & 7;
            cp_async16(sbase + (uint32_t)(KS_OFF + b * 64 * ALD + row * ALD + ch * 8) * 2u,
                       ksrc + row * HDIM + ch * 8);
            cp_async16(sbase + (uint32_t)(VS_OFF + b * 64 * ALD + row * ALD + ch * 8) * 2u,
                       vsrc + (size_t)row * SEQ + ch * 8);
        }
        CP_COMMIT();
    };

    issue_kv(0, 0);
    CP_WAIT(0);
    __syncthreads();

    // ---- Q fragments in registers (4 k-groups x 4 half2 regs) ----
    uint32_t qf[4][4];
#pragma unroll
    for (int kg = 0; kg < 4; kg++) {
        const __half* p = QP + (wm + grp) * ALD + kg * 16 + 2 * tig;
        qf[kg][0] = *reinterpret_cast<const uint32_t*>(p);
        qf[kg][1] = *reinterpret_cast<const uint32_t*>(p + 8 * ALD);
        qf[kg][2] = *reinterpret_cast<const uint32_t*>(p + 8);
        qf[kg][3] = *reinterpret_cast<const uint32_t*>(p + 8 * ALD + 8);
    }

    float m0 = -1e30f, m1 = -1e30f, l0 = 0.0f, l1 = 0.0f;
    float oa[8][4];
#pragma unroll
    for (int nt = 0; nt < 8; nt++)
#pragma unroll
        for (int i = 0; i < 4; i++) oa[nt][i] = 0.0f;

    for (int kt = 0; kt < NT_TILES; kt++) {
        const int buf = kt & 1;
        if (kt > 0) { CP_WAIT(0); __syncthreads(); }
        if (kt + 1 < NT_TILES) issue_kv(kt + 1, 1 - buf);

        // ---- S = Q @ K^T ----
        float sacc[8][4];
#pragma unroll
        for (int nt = 0; nt < 8; nt++)
#pragma unroll
            for (int i = 0; i < 4; i++) sacc[nt][i] = 0.0f;

        const __half* Kb = smh + KS_OFF + buf * 64 * ALD;
#pragma unroll
        for (int kg = 0; kg < 4; kg++) {
            uint32_t bf[8][2];
#pragma unroll
            for (int nt = 0; nt < 8; nt++) {
                const __half* p = Kb + (nt * 8 + grp) * ALD + kg * 16 + 2 * tig;
                bf[nt][0] = *reinterpret_cast<const uint32_t*>(p);
                bf[nt][1] = *reinterpret_cast<const uint32_t*>(p + 8);
            }
#pragma unroll
            for (int nt = 0; nt < 8; nt++)
                mma_f16(sacc[nt], qf[kg], bf[nt]);
        }

        // ---- online softmax on fragments ----
        float mx0 = -1e30f, mx1 = -1e30f;
#pragma unroll
        for (int nt = 0; nt < 8; nt++) {
            mx0 = fmaxf(mx0, fmaxf(sacc[nt][0], sacc[nt][1]));
            mx1 = fmaxf(mx1, fmaxf(sacc[nt][2], sacc[nt][3]));
        }
        mx0 = fmaxf(mx0, __shfl_xor_sync(0xffffffffu, mx0, 1));
        mx0 = fmaxf(mx0, __shfl_xor_sync(0xffffffffu, mx0, 2));
        mx1 = fmaxf(mx1, __shfl_xor_sync(0xffffffffu, mx1, 1));
        mx1 = fmaxf(mx1, __shfl_xor_sync(0xffffffffu, mx1, 2));
        const float mn0 = fmaxf(m0, mx0);
        const float mn1 = fmaxf(m1, mx1);
        const float c0 = __expf(m0 - mn0);
        const float c1 = __expf(m1 - mn1);
        m0 = mn0; m1 = mn1;

        __syncwarp();   // prior PV reads of P done before overwriting
        float s0 = 0.0f, s1 = 0.0f;
#pragma unroll
        for (int nt = 0; nt < 8; nt++) {
            float p00 = __expf(sacc[nt][0] - mn0);
            float p01 = __expf(sacc[nt][1] - mn0);
            float p10 = __expf(sacc[nt][2] - mn1);
            float p11 = __expf(sacc[nt][3] - mn1);
            s0 += p00 + p01;
            s1 += p10 + p11;
            *reinterpret_cast<__half2*>(QP + (wm + grp) * ALD + nt * 8 + 2 * tig) =
                __floats2half2_rn(p00, p01);
            *reinterpret_cast<__half2*>(QP + (wm + grp + 8) * ALD + nt * 8 + 2 * tig) =
                __floats2half2_rn(p10, p11);
        }
        s0 += __shfl_xor_sync(0xffffffffu, s0, 1);
        s0 += __shfl_xor_sync(0xffffffffu, s0, 2);
        s1 += __shfl_xor_sync(0xffffffffu, s1, 1);
        s1 += __shfl_xor_sync(0xffffffffu, s1, 2);
        l0 = l0 * c0 + s0;
        l1 = l1 * c1 + s1;
#pragma unroll
        for (int nt = 0; nt < 8; nt++) {
            oa[nt][0] *= c0; oa[nt][1] *= c0;
            oa[nt][2] *= c1; oa[nt][3] *= c1;
        }
        __syncwarp();   // P visible to all lanes of this warp

        // ---- O += P @ V  (B-fragments from V^T in smem) ----
        const __half* Vb = smh + VS_OFF + buf * 64 * ALD;
#pragma unroll
        for (int kg = 0; kg < 4; kg++) {
            uint32_t af[4];
            const __half* pp = QP + (wm + grp) * ALD + kg * 16 + 2 * tig;
            af[0] = *reinterpret_cast<const uint32_t*>(pp);
            af[1] = *reinterpret_cast<const uint32_t*>(pp + 8 * ALD);
            af[2] = *reinterpret_cast<const uint32_t*>(pp + 8);
            af[3] = *reinterpret_cast<const uint32_t*>(pp + 8 * ALD + 8);
#pragma unroll
            for (int nt = 0; nt < 8; nt++) {
                uint32_t bf2[2];
                const __half* vp = Vb + (nt * 8 + grp) * ALD + kg * 16 + 2 * tig;
                bf2[0] = *reinterpret_cast<const uint32_t*>(vp);
                bf2[1] = *reinterpret_cast<const uint32_t*>(vp + 8);
                mma_f16(oa[nt], af, bf2);
            }
        }
    }

    // ---- epilogue: normalize, RNA-round, write ctx [B,S,D] ----
    const float il0 = 1.0f / l0;
    const float il1 = 1.0f / l1;
    const int bq = bh >> 4;
    const int h = bh & (H - 1);
    const int gr0 = qt * 128 + wm + grp;
#pragma unroll
    for (int nt = 0; nt < 8; nt++) {
        const int col = h * HDIM + nt * 8 + 2 * tig;
        float2 v0, v1;
        v0.x = tf32r(oa[nt][0] * il0); v0.y = tf32r(oa[nt][1] * il0);
        v1.x = tf32r(oa[nt][2] * il1); v1.y = tf32r(oa[nt][3] * il1);
        *reinterpret_cast<float2*>(ctx + ((size_t)bq * SEQ + gr0) * D + col) = v0;
        *reinterpret_cast<float2*>(ctx + ((size_t)bq * SEQ + gr0 + 8) * D + col) = v1;
    }
}

// ============================================================
// Launch
// ============================================================
extern "C" void kernel_launch(void* const* d_in, const int* in_sizes, int n_in,
                              void* d_out, int out_size)
{
    const float* x  = (const float*)d_in[0];
    const float* Wq = (const float*)d_in[1];
    const float* bq = (const float*)d_in[2];
    const float* Wk = (const float*)d_in[3];
    const float* bk = (const float*)d_in[4];
    const float* Wv = (const float*)d_in[5];
    const float* bv = (const float*)d_in[6];
    const float* Wo = (const float*)d_in[7];
    const float* bo = (const float*)d_in[8];
    float* out = (float*)d_out;

    float *Ctxd, *Wtd, *xrd;
    __half *Qhd, *Khd, *Vthd;
    cudaGetSymbolAddress((void**)&Ctxd, g_ctx);
    cudaGetSymbolAddress((void**)&Wtd, g_Wt);
    cudaGetSymbolAddress((void**)&xrd, g_xr);
    cudaGetSymbolAddress((void**)&Qhd, g_Qh);
    cudaGetSymbolAddress((void**)&Khd, g_Kh);
    cudaGetSymbolAddress((void**)&Vthd, g_Vth);

    round_x<<<MROWS * D / 1024, 256>>>(x);
    transpose_all<<<dim3(D / 32, D / 32, 4), dim3(32, 8)>>>(Wq, Wk, Wv, Wo);

    cudaFuncSetAttribute(qkv_gemm, cudaFuncAttributeMaxDynamicSharedMemorySize, GEMM_SMEM);
    cudaFuncSetAttribute(o_gemm, cudaFuncAttributeMaxDynamicSharedMemorySize, GEMM_SMEM);
    qkv_gemm<<<dim3(24, MROWS / 128), 256, GEMM_SMEM>>>(xrd, bq, bk, bv);

    cudaFuncSetAttribute(attn_mma, cudaFuncAttributeMaxDynamicSharedMemorySize, ATT_SMEM);
    attn_mma<<<dim3(SEQ / 128, BATCH * H), 256, ATT_SMEM>>>(Qhd, Khd, Vthd, Ctxd);

    o_gemm<<<dim3(D / 128, MROWS / 128), 256, GEMM_SMEM>>>(Ctxd, Wtd + 3 * (size_t)D * D, bo, out);
}

// round 8
// speedup vs baseline: 6.9969x; 1.4825x over previous
#include <cuda_runtime.h>
#include <cuda_fp16.h>
#include <cstdint>

#define D 1024
#define H 16
#define HDIM 64
#define BATCH 2
#define SEQ 2048
#define MROWS (BATCH * SEQ) /* 4096 */

// ---------------- scratch (device globals; allocation-free) ----------------
__device__ __half g_xh[MROWS * D];               // fp16 x
__device__ __half g_Wth[4 * D * D];              // transposed fp16 weights [n][k]
__device__ __half g_Qh[BATCH * H * SEQ * HDIM];  // [bh][s][d], scaled 0.125*log2e
__device__ __half g_Kh[BATCH * H * SEQ * HDIM];  // [bh][s][d]
__device__ __half g_Vth[BATCH * H * HDIM * SEQ]; // [bh][d][s]
__device__ __half g_ctxh[MROWS * D];             // fp16 ctx [B,S,D]

// ---------------- helpers ----------------
__device__ __forceinline__ uint32_t smem_u32(const void* p) {
    uint32_t a;
    asm("{ .reg .u64 t; cvta.to.shared.u64 t, %1; cvt.u32.u64 %0, t; }"
        : "=r"(a) : "l"(p));
    return a;
}
__device__ __forceinline__ uint32_t h2u(__half2 h) {
    uint32_t u;
    __builtin_memcpy(&u, &h, 4);
    return u;
}
__device__ __forceinline__ void cp_async16(uint32_t dst, const void* src) {
    asm volatile("cp.async.cg.shared.global [%0], [%1], 16;" :: "r"(dst), "l"(src));
}
#define CP_COMMIT() asm volatile("cp.async.commit_group;" ::: "memory")
#define CP_WAIT(n)  asm volatile("cp.async.wait_group %0;" :: "n"(n) : "memory")

__device__ __forceinline__ void mma_f16(float* c, const uint32_t* a, const uint32_t* b) {
    asm volatile(
        "mma.sync.aligned.m16n8k16.row.col.f32.f16.f16.f32 "
        "{%0,%1,%2,%3}, {%4,%5,%6,%7}, {%8,%9}, {%0,%1,%2,%3};"
        : "+f"(c[0]), "+f"(c[1]), "+f"(c[2]), "+f"(c[3])
        : "r"(a[0]), "r"(a[1]), "r"(a[2]), "r"(a[3]), "r"(b[0]), "r"(b[1]));
}

// ============================================================
// Prep: x -> fp16
// ============================================================
__global__ __launch_bounds__(256) void round_xh(const float* __restrict__ x) {
    const int i = (blockIdx.x * 256 + threadIdx.x) * 8;
    float4 a = *reinterpret_cast<const float4*>(x + i);
    float4 b = *reinterpret_cast<const float4*>(x + i + 4);
    __half2 h[4];
    h[0] = __floats2half2_rn(a.x, a.y);
    h[1] = __floats2half2_rn(a.z, a.w);
    h[2] = __floats2half2_rn(b.x, b.y);
    h[3] = __floats2half2_rn(b.z, b.w);
    *reinterpret_cast<uint4*>(g_xh + i) = *reinterpret_cast<uint4*>(h);
}

// ============================================================
// All 4 weight transposes: Wth[n][k] = fp16(W[k][n])
// ============================================================
__global__ __launch_bounds__(256) void transpose_all(
    const float* __restrict__ W0, const float* __restrict__ W1,
    const float* __restrict__ W2, const float* __restrict__ W3) {
    __shared__ float t[32][33];
    const float* W = (blockIdx.z == 0) ? W0 : (blockIdx.z == 1) ? W1
                   : (blockIdx.z == 2) ? W2 : W3;
    __half* Wt = g_Wth + (size_t)blockIdx.z * D * D;
    const int bx = blockIdx.x * 32;
    const int by = blockIdx.y * 32;
    const int x = threadIdx.x;
    const int y = threadIdx.y;
#pragma unroll
    for (int i = 0; i < 4; i++)
        t[y + 8 * i][x] = W[(size_t)(by + y + 8 * i) * D + bx + x];
    __syncthreads();
#pragma unroll
    for (int i = 0; i < 4; i++)
        Wt[(size_t)(bx + y + 8 * i) * D + by + x] = __float2half_rn(t[x][y + 8 * i]);
}

// ============================================================
// fp16 mma.sync GEMM core: C[128x128] = A @ Bt^T
// K-chunk 64 halves, double-buffered cp.async; 8 warps (2x4),
// warp 64x32 = 4x4 m16n8k16 tiles.
// ============================================================
#define GKC 64
#define GALD 72                 /* halves per smem row */
#define GTILEH (128 * GALD)     /* halves per buffer */
#define GEMM_SMEM (4 * GTILEH * 2)

struct GemmAcc { float a[4][4][4]; };

__device__ __forceinline__ void gemm_core_h(
    const __half* __restrict__ A, const __half* __restrict__ Bt,
    int bm, int bn, __half* sm, GemmAcc& G)
{
    __half* As = sm;
    __half* Bs = sm + 2 * GTILEH;
    const uint32_t sa = smem_u32(As);
    const uint32_t sbb = smem_u32(Bs);

    const int tid = threadIdx.x;
    const int warp = tid >> 5;
    const int lane = tid & 31;
    const int grp = lane >> 2;
    const int tig = lane & 3;
    const int wm = (warp & 1) * 64;
    const int wn = (warp >> 1) * 32;

#pragma unroll
    for (int mt = 0; mt < 4; mt++)
#pragma unroll
        for (int nt = 0; nt < 4; nt++)
#pragma unroll
            for (int i = 0; i < 4; i++) G.a[mt][nt][i] = 0.0f;

    auto issue = [&](int chunk, int buf) {
        const int k0 = chunk * GKC;
#pragma unroll
        for (int i = 0; i < 4; i++) {
            const int s = tid + i * 256;   // 0..1023
            const int row = s >> 3;
            const int ch = s & 7;          // 8 chunks of 8 halves
            const uint32_t soff = (uint32_t)(buf * GTILEH + row * GALD + ch * 8) * 2u;
            cp_async16(sa + soff, A + (size_t)(bm + row) * D + k0 + ch * 8);
            cp_async16(sbb + soff, Bt + (size_t)(bn + row) * D + k0 + ch * 8);
        }
        CP_COMMIT();
    };

    issue(0, 0);

    const int NCHUNK = D / GKC;   // 16
    for (int c = 0; c < NCHUNK; c++) {
        const int buf = c & 1;
        if (c + 1 < NCHUNK) {
            issue(c + 1, 1 - buf);
            CP_WAIT(1);
        } else {
            CP_WAIT(0);
        }
        __syncthreads();

        const __half* Ab = As + buf * GTILEH;
        const __half* Bb = Bs + buf * GTILEH;
#pragma unroll
        for (int kg = 0; kg < 4; kg++) {
            uint32_t afr[4][4];
#pragma unroll
            for (int mt = 0; mt < 4; mt++) {
                const __half* p = Ab + (wm + mt * 16 + grp) * GALD + kg * 16 + 2 * tig;
                afr[mt][0] = *reinterpret_cast<const uint32_t*>(p);
                afr[mt][1] = *reinterpret_cast<const uint32_t*>(p + 8 * GALD);
                afr[mt][2] = *reinterpret_cast<const uint32_t*>(p + 8);
                afr[mt][3] = *reinterpret_cast<const uint32_t*>(p + 8 * GALD + 8);
            }
            uint32_t bfr[4][2];
#pragma unroll
            for (int nt = 0; nt < 4; nt++) {
                const __half* p = Bb + (wn + nt * 8 + grp) * GALD + kg * 16 + 2 * tig;
                bfr[nt][0] = *reinterpret_cast<const uint32_t*>(p);
                bfr[nt][1] = *reinterpret_cast<const uint32_t*>(p + 8);
            }
#pragma unroll
            for (int mt = 0; mt < 4; mt++)
#pragma unroll
                for (int nt = 0; nt < 4; nt++)
                    mma_f16(G.a[mt][nt], afr[mt], bfr[nt]);
        }
        __syncthreads();
    }
}

// ---- merged QKV projection: grid (24, 32) ----
#define QSCALE (0.125f * 1.44269504088896f)   /* fold 1/sqrt(64) and log2(e) */

__global__ __launch_bounds__(256, 2) void qkv_gemm(
    const __half* __restrict__ xh,
    const float* __restrict__ bqv, const float* __restrict__ bkv,
    const float* __restrict__ bvv)
{
    extern __shared__ char smraw[];
    __half* sm = reinterpret_cast<__half*>(smraw);
    const int sector = blockIdx.x >> 3;           // 0=Q,1=K,2=V
    const int bn = (blockIdx.x & 7) * 128;
    const int bm = blockIdx.y * 128;
    const __half* Bt = g_Wth + (size_t)sector * D * D;
    const float* bias = (sector == 0) ? bqv : (sector == 1) ? bkv : bvv;

    GemmAcc G;
    gemm_core_h(xh, Bt, bm, bn, sm, G);

    const int tid = threadIdx.x;
    const int warp = tid >> 5;
    const int lane = tid & 31;
    const int grp = lane >> 2;
    const int tig = lane & 3;
    const int wm = (warp & 1) * 64;
    const int wn = (warp >> 1) * 32;

#pragma unroll
    for (int mt = 0; mt < 4; mt++) {
#pragma unroll
        for (int nt = 0; nt < 4; nt++) {
            const int n = bn + wn + nt * 8 + 2 * tig;
            const float b0 = bias[n], b1 = bias[n + 1];
#pragma unroll
            for (int half = 0; half < 2; half++) {
                const int m = bm + wm + mt * 16 + grp + half * 8;
                const int bq = m >> 11;
                const int s = m & (SEQ - 1);
                const int h = n >> 6;
                const int hd = n & (HDIM - 1);
                const int bh = bq * H + h;
                float vx = G.a[mt][nt][half * 2 + 0] + b0;
                float vy = G.a[mt][nt][half * 2 + 1] + b1;
                if (sector == 0) {
                    *reinterpret_cast<__half2*>(
                        g_Qh + ((size_t)bh * SEQ + s) * HDIM + hd) =
                        __floats2half2_rn(vx * QSCALE, vy * QSCALE);
                } else if (sector == 1) {
                    *reinterpret_cast<__half2*>(
                        g_Kh + ((size_t)bh * SEQ + s) * HDIM + hd) =
                        __floats2half2_rn(vx, vy);
                } else {
                    g_Vth[((size_t)bh * HDIM + hd) * SEQ + s] = __float2half_rn(vx);
                    g_Vth[((size_t)bh * HDIM + hd + 1) * SEQ + s] = __float2half_rn(vy);
                }
            }
        }
    }
}

// ---- O projection: half in, float out ----
__global__ __launch_bounds__(256, 2) void o_gemm(
    const __half* __restrict__ A, const __half* __restrict__ Bt,
    const float* __restrict__ bias, float* __restrict__ Cout)
{
    extern __shared__ char smraw[];
    __half* sm = reinterpret_cast<__half*>(smraw);
    const int bn = blockIdx.x * 128;
    const int bm = blockIdx.y * 128;

    GemmAcc G;
    gemm_core_h(A, Bt, bm, bn, sm, G);

    const int tid = threadIdx.x;
    const int warp = tid >> 5;
    const int lane = tid & 31;
    const int grp = lane >> 2;
    const int tig = lane & 3;
    const int wm = (warp & 1) * 64;
    const int wn = (warp >> 1) * 32;

#pragma unroll
    for (int mt = 0; mt < 4; mt++) {
#pragma unroll
        for (int nt = 0; nt < 4; nt++) {
            const int n = bn + wn + nt * 8 + 2 * tig;
            const float b0 = bias[n], b1 = bias[n + 1];
#pragma unroll
            for (int half = 0; half < 2; half++) {
                const int m = bm + wm + mt * 16 + grp + half * 8;
                float2 v;
                v.x = G.a[mt][nt][half * 2 + 0] + b0;
                v.y = G.a[mt][nt][half * 2 + 1] + b1;
                *reinterpret_cast<float2*>(Cout + (size_t)m * D + n) = v;
            }
        }
    }
}

// ============================================================
// fp16 flash attention, register-resident P (FA2 fragment reuse)
// CTA: 128 q-rows x one (b,h); 8 warps x (16 rows x 64 cols).
// smem: K[2][64][72] | Vt[2][64][72] halves. Q frags from gmem.
// ============================================================
#define NT_TILES (SEQ / 64)   /* 32 */
#define ALD 72
#define KS_OFF 0
#define VS_OFF (2 * 64 * ALD)
#define ATT_SMEM ((4 * 64 * ALD) * 2)   /* 36864 bytes */

__global__ __launch_bounds__(256, 2) void attn_mma(
    const __half* __restrict__ Qg, const __half* __restrict__ Kg,
    const __half* __restrict__ Vtg, __half* __restrict__ ctxh)
{
    extern __shared__ char smraw[];
    __half* smh = reinterpret_cast<__half*>(smraw);
    const uint32_t sbase = smem_u32(smh);

    const int tid = threadIdx.x;
    const int warp = tid >> 5;
    const int lane = tid & 31;
    const int grp = lane >> 2;      // 0..7
    const int tig = lane & 3;       // 0..3
    const int wm = warp * 16;
    const int qt = blockIdx.x;      // 0..15
    const int bh = blockIdx.y;      // 0..31

    const __half* Qbase = Qg + ((size_t)bh * SEQ + qt * 128) * HDIM;
    const __half* Kbase = Kg + (size_t)bh * SEQ * HDIM;
    const __half* Vtbase = Vtg + (size_t)bh * HDIM * SEQ;

    auto issue_kv = [&](int kt, int b) {
        const __half* ksrc = Kbase + (size_t)kt * 64 * HDIM;
        const __half* vsrc = Vtbase + kt * 64;
#pragma unroll
        for (int i = 0; i < 2; i++) {
            const int s = tid + i * 256;      // 0..511
            const int row = s >> 3;
            const int ch = s & 7;
            cp_async16(sbase + (uint32_t)(KS_OFF + b * 64 * ALD + row * ALD + ch * 8) * 2u,
                       ksrc + row * HDIM + ch * 8);
            cp_async16(sbase + (uint32_t)(VS_OFF + b * 64 * ALD + row * ALD + ch * 8) * 2u,
                       vsrc + (size_t)row * SEQ + ch * 8);
        }
        CP_COMMIT();
    };

    issue_kv(0, 0);

    // ---- Q fragments direct from gmem (one-time, overlapped with cp.async) ----
    uint32_t qf[4][4];
    {
        const __half* q0 = Qbase + (wm + grp) * HDIM;
        const __half* q8 = q0 + 8 * HDIM;
#pragma unroll
        for (int kg = 0; kg < 4; kg++) {
            qf[kg][0] = *reinterpret_cast<const uint32_t*>(q0 + kg * 16 + 2 * tig);
            qf[kg][1] = *reinterpret_cast<const uint32_t*>(q8 + kg * 16 + 2 * tig);
            qf[kg][2] = *reinterpret_cast<const uint32_t*>(q0 + kg * 16 + 8 + 2 * tig);
            qf[kg][3] = *reinterpret_cast<const uint32_t*>(q8 + kg * 16 + 8 + 2 * tig);
        }
    }

    float m0 = -1e30f, m1 = -1e30f, l0 = 0.0f, l1 = 0.0f;
    float oa[8][4];
#pragma unroll
    for (int nt = 0; nt < 8; nt++)
#pragma unroll
        for (int i = 0; i < 4; i++) oa[nt][i] = 0.0f;

    CP_WAIT(0);
    __syncthreads();

    for (int kt = 0; kt < NT_TILES; kt++) {
        const int buf = kt & 1;
        if (kt > 0) { CP_WAIT(0); __syncthreads(); }
        if (kt + 1 < NT_TILES) issue_kv(kt + 1, 1 - buf);

        // ---- S = Q @ K^T  (logits already in base-2 domain) ----
        float sacc[8][4];
#pragma unroll
        for (int nt = 0; nt < 8; nt++)
#pragma unroll
            for (int i = 0; i < 4; i++) sacc[nt][i] = 0.0f;

        const __half* Kb = smh + KS_OFF + buf * 64 * ALD;
#pragma unroll
        for (int kg = 0; kg < 4; kg++) {
            uint32_t bf[8][2];
#pragma unroll
            for (int nt = 0; nt < 8; nt++) {
                const __half* p = Kb + (nt * 8 + grp) * ALD + kg * 16 + 2 * tig;
                bf[nt][0] = *reinterpret_cast<const uint32_t*>(p);
                bf[nt][1] = *reinterpret_cast<const uint32_t*>(p + 8);
            }
#pragma unroll
            for (int nt = 0; nt < 8; nt++)
                mma_f16(sacc[nt], qf[kg], bf[nt]);
        }

        // ---- online softmax (exp2) ----
        float mx0 = -1e30f, mx1 = -1e30f;
#pragma unroll
        for (int nt = 0; nt < 8; nt++) {
            mx0 = fmaxf(mx0, fmaxf(sacc[nt][0], sacc[nt][1]));
            mx1 = fmaxf(mx1, fmaxf(sacc[nt][2], sacc[nt][3]));
        }
        mx0 = fmaxf(mx0, __shfl_xor_sync(0xffffffffu, mx0, 1));
        mx0 = fmaxf(mx0, __shfl_xor_sync(0xffffffffu, mx0, 2));
        mx1 = fmaxf(mx1, __shfl_xor_sync(0xffffffffu, mx1, 1));
        mx1 = fmaxf(mx1, __shfl_xor_sync(0xffffffffu, mx1, 2));
        const float mn0 = fmaxf(m0, mx0);
        const float mn1 = fmaxf(m1, mx1);
        const float c0 = exp2f(m0 - mn0);
        const float c1 = exp2f(m1 - mn1);
        m0 = mn0; m1 = mn1;

        float s0 = 0.0f, s1 = 0.0f;
        uint32_t pf[8][2];   // P as half2: [nt]{(c0,c1),(c2,c3)}
#pragma unroll
        for (int nt = 0; nt < 8; nt++) {
            float p00 = exp2f(sacc[nt][0] - mn0);
            float p01 = exp2f(sacc[nt][1] - mn0);
            float p10 = exp2f(sacc[nt][2] - mn1);
            float p11 = exp2f(sacc[nt][3] - mn1);
            s0 += p00 + p01;
            s1 += p10 + p11;
            pf[nt][0] = h2u(__floats2half2_rn(p00, p01));
            pf[nt][1] = h2u(__floats2half2_rn(p10, p11));
        }
        s0 += __shfl_xor_sync(0xffffffffu, s0, 1);
        s0 += __shfl_xor_sync(0xffffffffu, s0, 2);
        s1 += __shfl_xor_sync(0xffffffffu, s1, 1);
        s1 += __shfl_xor_sync(0xffffffffu, s1, 2);
        l0 = l0 * c0 + s0;
        l1 = l1 * c1 + s1;
#pragma unroll
        for (int nt = 0; nt < 8; nt++) {
            oa[nt][0] *= c0; oa[nt][1] *= c0;
            oa[nt][2] *= c1; oa[nt][3] *= c1;
        }

        // ---- O += P @ V : A-fragments straight from pf registers ----
        const __half* Vb = smh + VS_OFF + buf * 64 * ALD;
#pragma unroll
        for (int kg = 0; kg < 4; kg++) {
            uint32_t af[4];
            af[0] = pf[2 * kg][0];
            af[1] = pf[2 * kg][1];
            af[2] = pf[2 * kg + 1][0];
            af[3] = pf[2 * kg + 1][1];
#pragma unroll
            for (int nt = 0; nt < 8; nt++) {
                uint32_t bf2[2];
                const __half* vp = Vb + (nt * 8 + grp) * ALD + kg * 16 + 2 * tig;
                bf2[0] = *reinterpret_cast<const uint32_t*>(vp);
                bf2[1] = *reinterpret_cast<const uint32_t*>(vp + 8);
                mma_f16(oa[nt], af, bf2);
            }
        }
    }

    // ---- epilogue: normalize, write half ctx [B,S,D] ----
    const float il0 = 1.0f / l0;
    const float il1 = 1.0f / l1;
    const int bq = bh >> 4;
    const int h = bh & (H - 1);
    const int gr0 = qt * 128 + wm + grp;
#pragma unroll
    for (int nt = 0; nt < 8; nt++) {
        const int col = h * HDIM + nt * 8 + 2 * tig;
        *reinterpret_cast<__half2*>(ctxh + ((size_t)bq * SEQ + gr0) * D + col) =
            __floats2half2_rn(oa[nt][0] * il0, oa[nt][1] * il0);
        *reinterpret_cast<__half2*>(ctxh + ((size_t)bq * SEQ + gr0 + 8) * D + col) =
            __floats2half2_rn(oa[nt][2] * il1, oa[nt][3] * il1);
    }
}

// ============================================================
// Launch
// ============================================================
extern "C" void kernel_launch(void* const* d_in, const int* in_sizes, int n_in,
                              void* d_out, int out_size)
{
    const float* x  = (const float*)d_in[0];
    const float* Wq = (const float*)d_in[1];
    const float* bq = (const float*)d_in[2];
    const float* Wk = (const float*)d_in[3];
    const float* bk = (const float*)d_in[4];
    const float* Wv = (const float*)d_in[5];
    const float* bv = (const float*)d_in[6];
    const float* Wo = (const float*)d_in[7];
    const float* bo = (const float*)d_in[8];
    float* out = (float*)d_out;

    __half *xhd, *Wthd, *Qhd, *Khd, *Vthd, *ctxhd;
    cudaGetSymbolAddress((void**)&xhd, g_xh);
    cudaGetSymbolAddress((void**)&Wthd, g_Wth);
    cudaGetSymbolAddress((void**)&Qhd, g_Qh);
    cudaGetSymbolAddress((void**)&Khd, g_Kh);
    cudaGetSymbolAddress((void**)&Vthd, g_Vth);
    cudaGetSymbolAddress((void**)&ctxhd, g_ctxh);

    round_xh<<<MROWS * D / 2048, 256>>>(x);
    transpose_all<<<dim3(D / 32, D / 32, 4), dim3(32, 8)>>>(Wq, Wk, Wv, Wo);

    cudaFuncSetAttribute(qkv_gemm, cudaFuncAttributeMaxDynamicSharedMemorySize, GEMM_SMEM);
    cudaFuncSetAttribute(o_gemm, cudaFuncAttributeMaxDynamicSharedMemorySize, GEMM_SMEM);
    qkv_gemm<<<dim3(24, MROWS / 128), 256, GEMM_SMEM>>>(xhd, bq, bk, bv);

    cudaFuncSetAttribute(attn_mma, cudaFuncAttributeMaxDynamicSharedMemorySize, ATT_SMEM);
    attn_mma<<<dim3(SEQ / 128, BATCH * H), 256, ATT_SMEM>>>(Qhd, Khd, Vthd, ctxhd);

    o_gemm<<<dim3(D / 128, MROWS / 128), 256, GEMM_SMEM>>>(ctxhd, Wthd + 3 * (size_t)D * D, bo, out);
}

// round 9
// speedup vs baseline: 7.6133x; 1.0881x over previous
#include <cuda_runtime.h>
#include <cuda_fp16.h>
#include <cstdint>

#define D 1024
#define H 16
#define HDIM 64
#define BATCH 2
#define SEQ 2048
#define MROWS (BATCH * SEQ) /* 4096 */

// ---------------- scratch (device globals; allocation-free) ----------------
__device__ __half g_xh[MROWS * D];               // fp16 x
__device__ __half g_Wth[4 * D * D];              // transposed fp16 weights [n][k]
__device__ __half g_Qh[BATCH * H * SEQ * HDIM];  // [bh][s][d], scaled 0.125*log2e
__device__ __half g_Kh[BATCH * H * SEQ * HDIM];  // [bh][s][d]
__device__ __half g_Vth[BATCH * H * HDIM * SEQ]; // [bh][d][s]
__device__ __half g_ctxh[MROWS * D];             // fp16 ctx [B,S,D]

// ---------------- helpers ----------------
__device__ __forceinline__ uint32_t smem_u32(const void* p) {
    uint32_t a;
    asm("{ .reg .u64 t; cvta.to.shared.u64 t, %1; cvt.u32.u64 %0, t; }"
        : "=r"(a) : "l"(p));
    return a;
}
__device__ __forceinline__ uint32_t h2u(__half2 h) {
    uint32_t u;
    __builtin_memcpy(&u, &h, 4);
    return u;
}
__device__ __forceinline__ void cp_async16(uint32_t dst, const void* src) {
    asm volatile("cp.async.cg.shared.global [%0], [%1], 16;" :: "r"(dst), "l"(src));
}
#define CP_COMMIT() asm volatile("cp.async.commit_group;" ::: "memory")
#define CP_WAIT(n)  asm volatile("cp.async.wait_group %0;" :: "n"(n) : "memory")

__device__ __forceinline__ void mma_f16(float* c, const uint32_t* a, const uint32_t* b) {
    asm volatile(
        "mma.sync.aligned.m16n8k16.row.col.f32.f16.f16.f32 "
        "{%0,%1,%2,%3}, {%4,%5,%6,%7}, {%8,%9}, {%0,%1,%2,%3};"
        : "+f"(c[0]), "+f"(c[1]), "+f"(c[2]), "+f"(c[3])
        : "r"(a[0]), "r"(a[1]), "r"(a[2]), "r"(a[3]), "r"(b[0]), "r"(b[1]));
}
__device__ __forceinline__ void ldsm_x4(uint32_t* r, uint32_t addr) {
    asm volatile("ldmatrix.sync.aligned.m8n8.x4.shared.b16 {%0,%1,%2,%3}, [%4];"
        : "=r"(r[0]), "=r"(r[1]), "=r"(r[2]), "=r"(r[3]) : "r"(addr));
}

// ============================================================
// Prep: x -> fp16
// ============================================================
__global__ __launch_bounds__(256) void round_xh(const float* __restrict__ x) {
    const int i = (blockIdx.x * 256 + threadIdx.x) * 8;
    float4 a = *reinterpret_cast<const float4*>(x + i);
    float4 b = *reinterpret_cast<const float4*>(x + i + 4);
    __half2 h[4];
    h[0] = __floats2half2_rn(a.x, a.y);
    h[1] = __floats2half2_rn(a.z, a.w);
    h[2] = __floats2half2_rn(b.x, b.y);
    h[3] = __floats2half2_rn(b.z, b.w);
    *reinterpret_cast<uint4*>(g_xh + i) = *reinterpret_cast<uint4*>(h);
}

// ============================================================
// All 4 weight transposes: Wth[n][k] = fp16(W[k][n])
// ============================================================
__global__ __launch_bounds__(256) void transpose_all(
    const float* __restrict__ W0, const float* __restrict__ W1,
    const float* __restrict__ W2, const float* __restrict__ W3) {
    __shared__ float t[32][33];
    const float* W = (blockIdx.z == 0) ? W0 : (blockIdx.z == 1) ? W1
                   : (blockIdx.z == 2) ? W2 : W3;
    __half* Wt = g_Wth + (size_t)blockIdx.z * D * D;
    const int bx = blockIdx.x * 32;
    const int by = blockIdx.y * 32;
    const int x = threadIdx.x;
    const int y = threadIdx.y;
#pragma unroll
    for (int i = 0; i < 4; i++)
        t[y + 8 * i][x] = W[(size_t)(by + y + 8 * i) * D + bx + x];
    __syncthreads();
#pragma unroll
    for (int i = 0; i < 4; i++)
        Wt[(size_t)(bx + y + 8 * i) * D + by + x] = __float2half_rn(t[x][y + 8 * i]);
}

// ============================================================
// fp16 mma.sync GEMM core with ldmatrix fragment loads
// C[128x128] = A @ Bt^T ; K-chunk 64 halves, double buffered.
// 8 warps (2x4), warp tile 64x32 = 4x4 m16n8k16.
// ============================================================
#define GKC 64
#define GALD 72                 /* halves per smem row */
#define GTILEH (128 * GALD)     /* halves per buffer */
#define GEMM_SMEM (4 * GTILEH * 2)

struct GemmAcc { float a[4][4][4]; };

__device__ __forceinline__ void gemm_core_h(
    const __half* __restrict__ A, const __half* __restrict__ Bt,
    int bm, int bn, __half* sm, GemmAcc& G)
{
    __half* As = sm;
    __half* Bs = sm + 2 * GTILEH;
    const uint32_t sa = smem_u32(As);
    const uint32_t sbb = smem_u32(Bs);

    const int tid = threadIdx.x;
    const int warp = tid >> 5;
    const int lane = tid & 31;
    const int g = lane >> 3;       // ldmatrix address group
    const int r = lane & 7;
    const int wm = (warp & 1) * 64;
    const int wn = (warp >> 1) * 32;

    // ldmatrix per-lane offsets (halves, within a buffer)
    // A groups: (m | g0:+0 g1:+8 | m, k | g2apply +8 on k for g>=2)
    const uint32_t aoff = (uint32_t)((wm + (g & 1) * 8 + r) * GALD + (g >> 1) * 8);
    // B groups: g0: n+r,k ; g1: n+r,k+8 ; g2: n+8+r,k ; g3: n+8+r,k+8
    const uint32_t boff = (uint32_t)((wn + (g >> 1) * 8 + r) * GALD + (g & 1) * 8);

#pragma unroll
    for (int mt = 0; mt < 4; mt++)
#pragma unroll
        for (int nt = 0; nt < 4; nt++)
#pragma unroll
            for (int i = 0; i < 4; i++) G.a[mt][nt][i] = 0.0f;

    auto issue = [&](int chunk, int buf) {
        const int k0 = chunk * GKC;
#pragma unroll
        for (int i = 0; i < 4; i++) {
            const int s = tid + i * 256;   // 0..1023
            const int row = s >> 3;
            const int ch = s & 7;          // 8 chunks of 8 halves
            const uint32_t soff = (uint32_t)(buf * GTILEH + row * GALD + ch * 8) * 2u;
            cp_async16(sa + soff, A + (size_t)(bm + row) * D + k0 + ch * 8);
            cp_async16(sbb + soff, Bt + (size_t)(bn + row) * D + k0 + ch * 8);
        }
        CP_COMMIT();
    };

    issue(0, 0);

    const int NCHUNK = D / GKC;   // 16
    for (int c = 0; c < NCHUNK; c++) {
        const int buf = c & 1;
        if (c + 1 < NCHUNK) {
            issue(c + 1, 1 - buf);
            CP_WAIT(1);
        } else {
            CP_WAIT(0);
        }
        __syncthreads();

        const uint32_t abase = sa + (uint32_t)(buf * GTILEH) * 2u;
        const uint32_t bbase = sbb + (uint32_t)(buf * GTILEH) * 2u;
#pragma unroll
        for (int kg = 0; kg < 4; kg++) {
            uint32_t afr[4][4];
#pragma unroll
            for (int mt = 0; mt < 4; mt++)
                ldsm_x4(afr[mt], abase + (aoff + mt * 16 * GALD + kg * 16) * 2u);
            uint32_t bfr[2][4];   // nt-pair: r0=b0(even) r1=b1(even) r2=b0(odd) r3=b1(odd)
#pragma unroll
            for (int nt2 = 0; nt2 < 2; nt2++)
                ldsm_x4(bfr[nt2], bbase + (boff + nt2 * 16 * GALD + kg * 16) * 2u);
#pragma unroll
            for (int mt = 0; mt < 4; mt++)
#pragma unroll
                for (int nt = 0; nt < 4; nt++)
                    mma_f16(G.a[mt][nt], afr[mt], &bfr[nt >> 1][(nt & 1) * 2]);
        }
        __syncthreads();
    }
}

// ---- merged QKV projection: grid (24, 32) ----
#define QSCALE (0.125f * 1.44269504088896f)   /* fold 1/sqrt(64) and log2(e) */

__global__ __launch_bounds__(256, 2) void qkv_gemm(
    const __half* __restrict__ xh,
    const float* __restrict__ bqv, const float* __restrict__ bkv,
    const float* __restrict__ bvv)
{
    extern __shared__ char smraw[];
    __half* sm = reinterpret_cast<__half*>(smraw);
    const int sector = blockIdx.x >> 3;           // 0=Q,1=K,2=V
    const int bn = (blockIdx.x & 7) * 128;
    const int bm = blockIdx.y * 128;
    const __half* Bt = g_Wth + (size_t)sector * D * D;
    const float* bias = (sector == 0) ? bqv : (sector == 1) ? bkv : bvv;

    GemmAcc G;
    gemm_core_h(xh, Bt, bm, bn, sm, G);

    const int tid = threadIdx.x;
    const int warp = tid >> 5;
    const int lane = tid & 31;
    const int grp = lane >> 2;
    const int tig = lane & 3;
    const int wm = (warp & 1) * 64;
    const int wn = (warp >> 1) * 32;

#pragma unroll
    for (int mt = 0; mt < 4; mt++) {
#pragma unroll
        for (int nt = 0; nt < 4; nt++) {
            const int n = bn + wn + nt * 8 + 2 * tig;
            const float b0 = bias[n], b1 = bias[n + 1];
#pragma unroll
            for (int half = 0; half < 2; half++) {
                const int m = bm + wm + mt * 16 + grp + half * 8;
                const int bq = m >> 11;
                const int s = m & (SEQ - 1);
                const int h = n >> 6;
                const int hd = n & (HDIM - 1);
                const int bh = bq * H + h;
                float vx = G.a[mt][nt][half * 2 + 0] + b0;
                float vy = G.a[mt][nt][half * 2 + 1] + b1;
                if (sector == 0) {
                    *reinterpret_cast<__half2*>(
                        g_Qh + ((size_t)bh * SEQ + s) * HDIM + hd) =
                        __floats2half2_rn(vx * QSCALE, vy * QSCALE);
                } else if (sector == 1) {
                    *reinterpret_cast<__half2*>(
                        g_Kh + ((size_t)bh * SEQ + s) * HDIM + hd) =
                        __floats2half2_rn(vx, vy);
                } else {
                    g_Vth[((size_t)bh * HDIM + hd) * SEQ + s] = __float2half_rn(vx);
                    g_Vth[((size_t)bh * HDIM + hd + 1) * SEQ + s] = __float2half_rn(vy);
                }
            }
        }
    }
}

// ---- O projection: half in, float out ----
__global__ __launch_bounds__(256, 2) void o_gemm(
    const __half* __restrict__ A, const __half* __restrict__ Bt,
    const float* __restrict__ bias, float* __restrict__ Cout)
{
    extern __shared__ char smraw[];
    __half* sm = reinterpret_cast<__half*>(smraw);
    const int bn = blockIdx.x * 128;
    const int bm = blockIdx.y * 128;

    GemmAcc G;
    gemm_core_h(A, Bt, bm, bn, sm, G);

    const int tid = threadIdx.x;
    const int warp = tid >> 5;
    const int lane = tid & 31;
    const int grp = lane >> 2;
    const int tig = lane & 3;
    const int wm = (warp & 1) * 64;
    const int wn = (warp >> 1) * 32;

#pragma unroll
    for (int mt = 0; mt < 4; mt++) {
#pragma unroll
        for (int nt = 0; nt < 4; nt++) {
            const int n = bn + wn + nt * 8 + 2 * tig;
            const float b0 = bias[n], b1 = bias[n + 1];
#pragma unroll
            for (int half = 0; half < 2; half++) {
                const int m = bm + wm + mt * 16 + grp + half * 8;
                float2 v;
                v.x = G.a[mt][nt][half * 2 + 0] + b0;
                v.y = G.a[mt][nt][half * 2 + 1] + b1;
                *reinterpret_cast<float2*>(Cout + (size_t)m * D + n) = v;
            }
        }
    }
}

// ============================================================
// fp16 flash attention: register P + ldmatrix K/V fragments
// CTA: 128 q-rows x one (b,h); 8 warps x (16 rows x 64 cols).
// smem: K[2][64][72] | Vt[2][64][72] halves.
// ============================================================
#define NT_TILES (SEQ / 64)   /* 32 */
#define ALD 72
#define KS_OFF 0
#define VS_OFF (2 * 64 * ALD)
#define ATT_SMEM ((4 * 64 * ALD) * 2)   /* 36864 bytes */

__global__ __launch_bounds__(256, 2) void attn_mma(
    const __half* __restrict__ Qg, const __half* __restrict__ Kg,
    const __half* __restrict__ Vtg, __half* __restrict__ ctxh)
{
    extern __shared__ char smraw[];
    __half* smh = reinterpret_cast<__half*>(smraw);
    const uint32_t sbase = smem_u32(smh);

    const int tid = threadIdx.x;
    const int warp = tid >> 5;
    const int lane = tid & 31;
    const int grp = lane >> 2;      // 0..7
    const int tig = lane & 3;       // 0..3
    const int g = lane >> 3;        // ldmatrix group
    const int r = lane & 7;
    const int wm = warp * 16;
    const int qt = blockIdx.x;      // 0..15
    const int bh = blockIdx.y;      // 0..31

    // B-operand ldmatrix offset (halves, within one 64x72 tile)
    const uint32_t boff = (uint32_t)(((g >> 1) * 8 + r) * ALD + (g & 1) * 8);

    const __half* Qbase = Qg + ((size_t)bh * SEQ + qt * 128) * HDIM;
    const __half* Kbase = Kg + (size_t)bh * SEQ * HDIM;
    const __half* Vtbase = Vtg + (size_t)bh * HDIM * SEQ;

    auto issue_kv = [&](int kt, int b) {
        const __half* ksrc = Kbase + (size_t)kt * 64 * HDIM;
        const __half* vsrc = Vtbase + kt * 64;
#pragma unroll
        for (int i = 0; i < 2; i++) {
            const int s = tid + i * 256;      // 0..511
            const int row = s >> 3;
            const int ch = s & 7;
            cp_async16(sbase + (uint32_t)(KS_OFF + b * 64 * ALD + row * ALD + ch * 8) * 2u,
                       ksrc + row * HDIM + ch * 8);
            cp_async16(sbase + (uint32_t)(VS_OFF + b * 64 * ALD + row * ALD + ch * 8) * 2u,
                       vsrc + (size_t)row * SEQ + ch * 8);
        }
        CP_COMMIT();
    };

    issue_kv(0, 0);

    // ---- Q fragments direct from gmem ----
    uint32_t qf[4][4];
    {
        const __half* q0 = Qbase + (wm + grp) * HDIM;
        const __half* q8 = q0 + 8 * HDIM;
#pragma unroll
        for (int kg = 0; kg < 4; kg++) {
            qf[kg][0] = *reinterpret_cast<const uint32_t*>(q0 + kg * 16 + 2 * tig);
            qf[kg][1] = *reinterpret_cast<const uint32_t*>(q8 + kg * 16 + 2 * tig);
            qf[kg][2] = *reinterpret_cast<const uint32_t*>(q0 + kg * 16 + 8 + 2 * tig);
            qf[kg][3] = *reinterpret_cast<const uint32_t*>(q8 + kg * 16 + 8 + 2 * tig);
        }
    }

    float m0 = -1e30f, m1 = -1e30f, l0 = 0.0f, l1 = 0.0f;
    float oa[8][4];
#pragma unroll
    for (int nt = 0; nt < 8; nt++)
#pragma unroll
        for (int i = 0; i < 4; i++) oa[nt][i] = 0.0f;

    CP_WAIT(0);
    __syncthreads();

    for (int kt = 0; kt < NT_TILES; kt++) {
        const int buf = kt & 1;
        if (kt > 0) { CP_WAIT(0); __syncthreads(); }
        if (kt + 1 < NT_TILES) issue_kv(kt + 1, 1 - buf);

        // ---- S = Q @ K^T ----
        float sacc[8][4];
#pragma unroll
        for (int nt = 0; nt < 8; nt++)
#pragma unroll
            for (int i = 0; i < 4; i++) sacc[nt][i] = 0.0f;

        const uint32_t kb = sbase + (uint32_t)(KS_OFF + buf * 64 * ALD) * 2u;
#pragma unroll
        for (int kg = 0; kg < 4; kg++) {
            uint32_t bf[4][4];    // nt-pairs
#pragma unroll
            for (int nt2 = 0; nt2 < 4; nt2++)
                ldsm_x4(bf[nt2], kb + (boff + nt2 * 16 * ALD + kg * 16) * 2u);
#pragma unroll
            for (int nt = 0; nt < 8; nt++)
                mma_f16(sacc[nt], qf[kg], &bf[nt >> 1][(nt & 1) * 2]);
        }

        // ---- online softmax (exp2 domain) ----
        float mx0 = -1e30f, mx1 = -1e30f;
#pragma unroll
        for (int nt = 0; nt < 8; nt++) {
            mx0 = fmaxf(mx0, fmaxf(sacc[nt][0], sacc[nt][1]));
            mx1 = fmaxf(mx1, fmaxf(sacc[nt][2], sacc[nt][3]));
        }
        mx0 = fmaxf(mx0, __shfl_xor_sync(0xffffffffu, mx0, 1));
        mx0 = fmaxf(mx0, __shfl_xor_sync(0xffffffffu, mx0, 2));
        mx1 = fmaxf(mx1, __shfl_xor_sync(0xffffffffu, mx1, 1));
        mx1 = fmaxf(mx1, __shfl_xor_sync(0xffffffffu, mx1, 2));
        const float mn0 = fmaxf(m0, mx0);
        const float mn1 = fmaxf(m1, mx1);
        const float c0 = exp2f(m0 - mn0);
        const float c1 = exp2f(m1 - mn1);
        m0 = mn0; m1 = mn1;

        float s0 = 0.0f, s1 = 0.0f;
        uint32_t pf[8][2];   // P as half2
#pragma unroll
        for (int nt = 0; nt < 8; nt++) {
            float p00 = exp2f(sacc[nt][0] - mn0);
            float p01 = exp2f(sacc[nt][1] - mn0);
            float p10 = exp2f(sacc[nt][2] - mn1);
            float p11 = exp2f(sacc[nt][3] - mn1);
            s0 += p00 + p01;
            s1 += p10 + p11;
            pf[nt][0] = h2u(__floats2half2_rn(p00, p01));
            pf[nt][1] = h2u(__floats2half2_rn(p10, p11));
        }
        s0 += __shfl_xor_sync(0xffffffffu, s0, 1);
        s0 += __shfl_xor_sync(0xffffffffu, s0, 2);
        s1 += __shfl_xor_sync(0xffffffffu, s1, 1);
        s1 += __shfl_xor_sync(0xffffffffu, s1, 2);
        l0 = l0 * c0 + s0;
        l1 = l1 * c1 + s1;
#pragma unroll
        for (int nt = 0; nt < 8; nt++) {
            oa[nt][0] *= c0; oa[nt][1] *= c0;
            oa[nt][2] *= c1; oa[nt][3] *= c1;
        }

        // ---- O += P @ V ----
        const uint32_t vb = sbase + (uint32_t)(VS_OFF + buf * 64 * ALD) * 2u;
#pragma unroll
        for (int kg = 0; kg < 4; kg++) {
            uint32_t af[4];
            af[0] = pf[2 * kg][0];
            af[1] = pf[2 * kg][1];
            af[2] = pf[2 * kg + 1][0];
            af[3] = pf[2 * kg + 1][1];
            uint32_t bf[4][4];
#pragma unroll
            for (int nt2 = 0; nt2 < 4; nt2++)
                ldsm_x4(bf[nt2], vb + (boff + nt2 * 16 * ALD + kg * 16) * 2u);
#pragma unroll
            for (int nt = 0; nt < 8; nt++)
                mma_f16(oa[nt], af, &bf[nt >> 1][(nt & 1) * 2]);
        }
    }

    // ---- epilogue: normalize, write half ctx [B,S,D] ----
    const float il0 = 1.0f / l0;
    const float il1 = 1.0f / l1;
    const int bq = bh >> 4;
    const int h = bh & (H - 1);
    const int gr0 = qt * 128 + wm + grp;
#pragma unroll
    for (int nt = 0; nt < 8; nt++) {
        const int col = h * HDIM + nt * 8 + 2 * tig;
        *reinterpret_cast<__half2*>(ctxh + ((size_t)bq * SEQ + gr0) * D + col) =
            __floats2half2_rn(oa[nt][0] * il0, oa[nt][1] * il0);
        *reinterpret_cast<__half2*>(ctxh + ((size_t)bq * SEQ + gr0 + 8) * D + col) =
            __floats2half2_rn(oa[nt][2] * il1, oa[nt][3] * il1);
    }
}

// ============================================================
// Launch
// ============================================================
extern "C" void kernel_launch(void* const* d_in, const int* in_sizes, int n_in,
                              void* d_out, int out_size)
{
    const float* x  = (const float*)d_in[0];
    const float* Wq = (const float*)d_in[1];
    const float* bq = (const float*)d_in[2];
    const float* Wk = (const float*)d_in[3];
    const float* bk = (const float*)d_in[4];
    const float* Wv = (const float*)d_in[5];
    const float* bv = (const float*)d_in[6];
    const float* Wo = (const float*)d_in[7];
    const float* bo = (const float*)d_in[8];
    float* out = (float*)d_out;

    __half *xhd, *Wthd, *Qhd, *Khd, *Vthd, *ctxhd;
    cudaGetSymbolAddress((void**)&xhd, g_xh);
    cudaGetSymbolAddress((void**)&Wthd, g_Wth);
    cudaGetSymbolAddress((void**)&Qhd, g_Qh);
    cudaGetSymbolAddress((void**)&Khd, g_Kh);
    cudaGetSymbolAddress((void**)&Vthd, g_Vth);
    cudaGetSymbolAddress((void**)&ctxhd, g_ctxh);

    round_xh<<<MROWS * D / 2048, 256>>>(x);
    transpose_all<<<dim3(D / 32, D / 32, 4), dim3(32, 8)>>>(Wq, Wk, Wv, Wo);

    cudaFuncSetAttribute(qkv_gemm, cudaFuncAttributeMaxDynamicSharedMemorySize, GEMM_SMEM);
    cudaFuncSetAttribute(o_gemm, cudaFuncAttributeMaxDynamicSharedMemorySize, GEMM_SMEM);
    qkv_gemm<<<dim3(24, MROWS / 128), 256, GEMM_SMEM>>>(xhd, bq, bk, bv);

    cudaFuncSetAttribute(attn_mma, cudaFuncAttributeMaxDynamicSharedMemorySize, ATT_SMEM);
    attn_mma<<<dim3(SEQ / 128, BATCH * H), 256, ATT_SMEM>>>(Qhd, Khd, Vthd, ctxhd);

    o_gemm<<<dim3(D / 128, MROWS / 128), 256, GEMM_SMEM>>>(ctxhd, Wthd + 3 * (size_t)D * D, bo, out);
}